// round 1
// baseline (speedup 1.0000x reference)
#include <cuda_runtime.h>
#include <math.h>

#define BB 2
#define NN 2048
#define CC 1024
#define HH 16
#define DD 64

// Scratch (device globals: allocation-free per harness rules)
__device__ float g_q[BB*HH*NN*DD];    // [B,H,N,D]
__device__ float g_k[BB*HH*NN*DD];
__device__ float g_v[BB*HH*NN*DD];
__device__ float g_ao[BB*NN*CC];      // [B,N,H*D] attention output

// ---------------------------------------------------------------------------
// SGEMM: 128x128 tile, BK=16, 256 threads, 8x8 per-thread (split-tile layout)
// MODE 0: qkv = x @ w_qkv, scatter into g_q/g_k/g_v  (Nn=3072)
// MODE 1: out = g_ao @ w_proj + bias                  (Nn=1024)
// ---------------------------------------------------------------------------
template<int MODE>
__global__ __launch_bounds__(256, 2)
void sgemm_kernel(const float* __restrict__ Ain,
                  const float* __restrict__ Bm,
                  const float* __restrict__ bias,
                  float* __restrict__ Cout)
{
    constexpr int K  = 1024;
    constexpr int Nn = (MODE == 0) ? 3072 : 1024;
    constexpr int BM = 128, BN = 128, BK = 16;

    __shared__ float As[BK][BM + 4];
    __shared__ float Bs[BK][BN];

    const float* A = (MODE == 1) ? g_ao : Ain;

    const int tid  = threadIdx.x;
    const int cRow = blockIdx.y;
    const int cCol = blockIdx.x;
    const int tx   = tid & 15;
    const int ty   = tid >> 4;

    const int aRow = tid >> 2;          // 0..63
    const int aCol = (tid & 3) << 2;    // 0,4,8,12
    const int bRow = tid >> 5;          // 0..7
    const int bCol = (tid & 31) << 2;   // 0..124

    const float* Ablk = A + (size_t)cRow * BM * K;
    const float* Bblk = Bm + cCol * BN;

    float acc[8][8];
    #pragma unroll
    for (int i = 0; i < 8; ++i)
        #pragma unroll
        for (int j = 0; j < 8; ++j) acc[i][j] = 0.0f;

    for (int k0 = 0; k0 < K; k0 += BK) {
        #pragma unroll
        for (int s = 0; s < 2; ++s) {
            int r = aRow + s * 64;
            float4 v = *(const float4*)(Ablk + (size_t)r * K + k0 + aCol);
            As[aCol + 0][r] = v.x;
            As[aCol + 1][r] = v.y;
            As[aCol + 2][r] = v.z;
            As[aCol + 3][r] = v.w;
        }
        #pragma unroll
        for (int s = 0; s < 2; ++s) {
            int r = bRow + s * 8;
            *(float4*)&Bs[r][bCol] =
                *(const float4*)(Bblk + (size_t)(k0 + r) * Nn + bCol);
        }
        __syncthreads();

        #pragma unroll
        for (int kk = 0; kk < BK; ++kk) {
            float ra[8], rb[8];
            *(float4*)&ra[0] = *(float4*)&As[kk][ty * 4];
            *(float4*)&ra[4] = *(float4*)&As[kk][64 + ty * 4];
            *(float4*)&rb[0] = *(float4*)&Bs[kk][tx * 4];
            *(float4*)&rb[4] = *(float4*)&Bs[kk][64 + tx * 4];
            #pragma unroll
            for (int i = 0; i < 8; ++i)
                #pragma unroll
                for (int j = 0; j < 8; ++j)
                    acc[i][j] = fmaf(ra[i], rb[j], acc[i][j]);
        }
        __syncthreads();
    }

    // epilogue
    #pragma unroll
    for (int i = 0; i < 8; ++i) {
        int rl = (i < 4) ? (ty * 4 + i) : (64 + ty * 4 + (i - 4));
        int r  = cRow * BM + rl;
        #pragma unroll
        for (int j = 0; j < 8; ++j) {
            int cl = (j < 4) ? (tx * 4 + j) : (64 + tx * 4 + (j - 4));
            int c  = cCol * BN + cl;
            float val = acc[i][j];
            if (MODE == 0) {
                int b     = r >> 11;        // n = 2048 rows per batch
                int n     = r & 2047;
                int which = c >> 10;        // 0=q 1=k 2=v
                int head  = (c >> 6) & 15;
                int dd    = c & 63;
                size_t idx = ((size_t)((b * HH + head) * NN + n)) * DD + dd;
                if (which == 0)      g_q[idx] = val;
                else if (which == 1) g_k[idx] = val;
                else                 g_v[idx] = val;
            } else {
                Cout[(size_t)r * Nn + c] = val + bias[c];
            }
        }
    }
}

// ---------------------------------------------------------------------------
// Per-head LayerNorm over D=64 on q and k; q additionally scaled by sqrt(D)=8.
// One warp per row; 4 warps per block.
// ---------------------------------------------------------------------------
__global__ __launch_bounds__(128)
void qk_ln_kernel(const float* __restrict__ ln_w, const float* __restrict__ ln_b)
{
    const int R = BB * HH * NN;                    // rows per tensor
    int row  = blockIdx.x * 4 + (threadIdx.x >> 5);
    int lane = threadIdx.x & 31;

    float* base  = (row < R) ? g_q : g_k;
    float  extra = (row < R) ? 8.0f : 1.0f;        // sqrt(64) fold into q
    int    r     = (row < R) ? row : (row - R);

    float* p = base + (size_t)r * DD;
    float x0 = p[lane];
    float x1 = p[lane + 32];
    float s  = x0 + x1;
    float ss = x0 * x0 + x1 * x1;
    #pragma unroll
    for (int o = 16; o > 0; o >>= 1) {
        s  += __shfl_xor_sync(0xffffffffu, s,  o);
        ss += __shfl_xor_sync(0xffffffffu, ss, o);
    }
    float mu  = s * (1.0f / 64.0f);
    float var = ss * (1.0f / 64.0f) - mu * mu;
    float inv = rsqrtf(var + 1e-5f);
    p[lane]      = ((x0 - mu) * inv * ln_w[lane]      + ln_b[lane])      * extra;
    p[lane + 32] = ((x1 - mu) * inv * ln_w[lane + 32] + ln_b[lane + 32]) * extra;
}

// ---------------------------------------------------------------------------
// Causal flash attention. Per CTA: 64 query rows of one (b,h); stream 64-key
// tiles with online softmax. 256 threads = 16x16; thread owns 4 rows x 4 cols.
// Writes [B,N,H,D] to g_ao.
// ---------------------------------------------------------------------------
#define FLD 68   // smem row stride (floats): 16B-aligned, conflict-benign

__global__ __launch_bounds__(256)
void flash_kernel()
{
    extern __shared__ float sm[];
    float* Qs = sm;                    // 64 x FLD
    float* Ks = Qs + 64 * FLD;
    float* Vs = Ks + 64 * FLD;
    float* Ps = Vs + 64 * FLD;

    const int bh  = blockIdx.y;        // b*H + h
    const int qi  = blockIdx.x;        // query tile
    const int tid = threadIdx.x;
    const int tx  = tid & 15;
    const int ty  = tid >> 4;

    const float* Qg = g_q + (size_t)bh * NN * DD + (size_t)qi * 64 * DD;
    const float* Kg = g_k + (size_t)bh * NN * DD;
    const float* Vg = g_v + (size_t)bh * NN * DD;

    // load Q tile (4096 floats -> 4 float4 per thread)
    #pragma unroll
    for (int s = 0; s < 4; ++s) {
        int idx = tid + s * 256;       // float4 index
        int r = idx >> 4;
        int c = (idx & 15) << 2;
        *(float4*)&Qs[r * FLD + c] = *(const float4*)(Qg + r * DD + c);
    }

    float m_i[4], l_i[4], o[4][4];
    #pragma unroll
    for (int i = 0; i < 4; ++i) {
        m_i[i] = -1e30f;
        l_i[i] = 0.0f;
        #pragma unroll
        for (int j = 0; j < 4; ++j) o[i][j] = 0.0f;
    }

    for (int kj = 0; kj <= qi; ++kj) {
        __syncthreads();   // previous-iteration consumers done (also covers Q load)
        const float* kg = Kg + (size_t)kj * 64 * DD;
        const float* vg = Vg + (size_t)kj * 64 * DD;
        #pragma unroll
        for (int s = 0; s < 4; ++s) {
            int idx = tid + s * 256;
            int r = idx >> 4;
            int c = (idx & 15) << 2;
            *(float4*)&Ks[r * FLD + c] = *(const float4*)(kg + r * DD + c);
            *(float4*)&Vs[r * FLD + c] = *(const float4*)(vg + r * DD + c);
        }
        __syncthreads();

        // S = Q K^T  (thread: rows ty*4..+3, key-cols tx*4..+3)
        float s4[4][4];
        #pragma unroll
        for (int i = 0; i < 4; ++i)
            #pragma unroll
            for (int j = 0; j < 4; ++j) s4[i][j] = 0.0f;

        #pragma unroll
        for (int k4 = 0; k4 < 64; k4 += 4) {
            float a[4][4], b[4][4];
            #pragma unroll
            for (int i = 0; i < 4; ++i)
                *(float4*)&a[i][0] = *(float4*)&Qs[(ty * 4 + i) * FLD + k4];
            #pragma unroll
            for (int j = 0; j < 4; ++j)
                *(float4*)&b[j][0] = *(float4*)&Ks[(tx * 4 + j) * FLD + k4];
            #pragma unroll
            for (int i = 0; i < 4; ++i)
                #pragma unroll
                for (int j = 0; j < 4; ++j)
                    #pragma unroll
                    for (int kk = 0; kk < 4; ++kk)
                        s4[i][j] = fmaf(a[i][kk], b[j][kk], s4[i][j]);
        }

        if (kj == qi) {   // diagonal tile causal mask: valid iff q_row >= k_col
            #pragma unroll
            for (int i = 0; i < 4; ++i)
                #pragma unroll
                for (int j = 0; j < 4; ++j)
                    if ((ty * 4 + i) < (tx * 4 + j)) s4[i][j] = -1e30f;
        }

        // online softmax per row (rows replicated across the 16 tx threads)
        #pragma unroll
        for (int i = 0; i < 4; ++i) {
            float mx = fmaxf(fmaxf(s4[i][0], s4[i][1]), fmaxf(s4[i][2], s4[i][3]));
            #pragma unroll
            for (int off = 8; off > 0; off >>= 1)
                mx = fmaxf(mx, __shfl_xor_sync(0xffffffffu, mx, off));
            float mnew  = fmaxf(m_i[i], mx);
            float alpha = __expf(m_i[i] - mnew);
            m_i[i] = mnew;
            float rs = 0.0f;
            #pragma unroll
            for (int j = 0; j < 4; ++j) {
                float pv = __expf(s4[i][j] - mnew);
                s4[i][j] = pv;
                rs += pv;
            }
            #pragma unroll
            for (int off = 8; off > 0; off >>= 1)
                rs += __shfl_xor_sync(0xffffffffu, rs, off);
            l_i[i] = l_i[i] * alpha + rs;
            #pragma unroll
            for (int j = 0; j < 4; ++j) o[i][j] *= alpha;
            float4 pr = make_float4(s4[i][0], s4[i][1], s4[i][2], s4[i][3]);
            *(float4*)&Ps[(ty * 4 + i) * FLD + tx * 4] = pr;
        }
        __syncthreads();

        // O += P @ V  (thread: rows ty*4..+3, d-cols tx*4..+3)
        #pragma unroll
        for (int k4 = 0; k4 < 64; k4 += 4) {
            float p[4][4], v[4][4];
            #pragma unroll
            for (int i = 0; i < 4; ++i)
                *(float4*)&p[i][0] = *(float4*)&Ps[(ty * 4 + i) * FLD + k4];
            #pragma unroll
            for (int kk = 0; kk < 4; ++kk)
                *(float4*)&v[kk][0] = *(float4*)&Vs[(k4 + kk) * FLD + tx * 4];
            #pragma unroll
            for (int i = 0; i < 4; ++i)
                #pragma unroll
                for (int j = 0; j < 4; ++j)
                    #pragma unroll
                    for (int kk = 0; kk < 4; ++kk)
                        o[i][j] = fmaf(p[i][kk], v[kk][j], o[i][j]);
        }
    }

    // finalize and scatter to [B,N,H,D]
    const int b = bh >> 4;
    const int h = bh & 15;
    #pragma unroll
    for (int i = 0; i < 4; ++i) {
        float inv = 1.0f / l_i[i];
        int n = qi * 64 + ty * 4 + i;
        size_t off = (((size_t)b * NN + n) * HH + h) * DD + tx * 4;
        float4 r = make_float4(o[i][0] * inv, o[i][1] * inv,
                               o[i][2] * inv, o[i][3] * inv);
        *(float4*)&g_ao[off] = r;
    }
}

// ---------------------------------------------------------------------------
extern "C" void kernel_launch(void* const* d_in, const int* in_sizes, int n_in,
                              void* d_out, int out_size)
{
    const float* x      = (const float*)d_in[0];
    const float* w_qkv  = (const float*)d_in[1];
    const float* w_proj = (const float*)d_in[2];
    const float* b_proj = (const float*)d_in[3];
    const float* ln_w   = (const float*)d_in[4];
    const float* ln_b   = (const float*)d_in[5];
    float* out = (float*)d_out;

    // 1) QKV projection + scatter
    dim3 g1(3 * CC / 128, (BB * NN) / 128);
    sgemm_kernel<0><<<g1, 256>>>(x, w_qkv, nullptr, nullptr);

    // 2) per-head LayerNorm on q,k (+ sqrt(D) on q)
    qk_ln_kernel<<<(2 * BB * HH * NN) / 4, 128>>>(ln_w, ln_b);

    // 3) causal flash attention
    size_t smem = 4 * 64 * FLD * sizeof(float);   // ~69.6 KB
    cudaFuncSetAttribute(flash_kernel,
                         cudaFuncAttributeMaxDynamicSharedMemorySize, (int)smem);
    flash_kernel<<<dim3(NN / 64, BB * HH), 256, smem>>>();

    // 4) output projection + bias
    dim3 g2(CC / 128, (BB * NN) / 128);
    sgemm_kernel<1><<<g2, 256>>>(nullptr, w_proj, b_proj, out);
}

// round 4
// speedup vs baseline: 1.0273x; 1.0273x over previous
#include <cuda_runtime.h>
#include <math.h>
#include <stdint.h>

#define BB 2
#define NN 2048
#define CC 1024
#define HH 16
#define DD 64

// Scratch (device globals: allocation-free per harness rules)
__device__ float g_q[BB*HH*NN*DD];    // [B,H,N,D]
__device__ float g_k[BB*HH*NN*DD];
__device__ float g_v[BB*HH*NN*DD];
__device__ float g_ao[BB*NN*CC];      // [B,N,(H D)] attention output

// ===========================================================================
// helpers
// ===========================================================================
__device__ __forceinline__ uint32_t f2tf32(float x) {
    uint32_t r;
    asm("cvt.rna.tf32.f32 %0, %1;" : "=r"(r) : "f"(x));
    return r;
}
__device__ __forceinline__ void mma1688(float* d, const uint32_t* a, const uint32_t* b) {
    asm volatile(
        "mma.sync.aligned.m16n8k8.row.col.f32.tf32.tf32.f32 "
        "{%0,%1,%2,%3}, {%4,%5,%6,%7}, {%8,%9}, {%0,%1,%2,%3};"
        : "+f"(d[0]), "+f"(d[1]), "+f"(d[2]), "+f"(d[3])
        : "r"(a[0]), "r"(a[1]), "r"(a[2]), "r"(a[3]), "r"(b[0]), "r"(b[1]));
}

// ===========================================================================
// 3xTF32 mma.sync GEMM:  C[4096 x Nn] = A[4096 x 1024] @ W[1024 x Nn]
// CTA 128x128, BK=16 double-buffered. 8 warps in 2(m) x 4(n); warp = 64x32.
// Each operand split hi/lo; acc += ah*bh + al*bh + ah*bl  (fp32-grade).
// SMEM strides: As 20 floats/row (bank = g*4+tig, conflict-free),
//               Bs 136 floats/row (bank = tig*8+g, conflict-free).
// MODE 0: A=x, W=w_qkv (Nn=3072), scatter epilogue -> g_q/g_k/g_v [B,H,N,D]
// MODE 1: A=g_ao, W=w_proj (Nn=1024), +bias -> Cout
// ===========================================================================
#define ASTRIDE 20
#define BSTRIDE 136
#define ABUF (128 * ASTRIDE)                 // 2560 u32 (one of hi/lo)
#define BBUF (16 * BSTRIDE)                  // 2176 u32
#define BUFU (2 * ABUF + 2 * BBUF)           // 9472 u32 per stage
#define GEMM_SMEM (2 * BUFU * 4)             // 75776 B

template<int MODE>
__global__ __launch_bounds__(256)
void tc_gemm(const float* __restrict__ Ain, const float* __restrict__ W,
             const float* __restrict__ bias, float* __restrict__ Cout)
{
    constexpr int K  = 1024;
    constexpr int NC = K / 16;                   // 64 chunks
    constexpr int Nn = (MODE == 0) ? 3072 : 1024;

    extern __shared__ uint32_t sm[];

    const int tid  = threadIdx.x;
    const int wid  = tid >> 5, lane = tid & 31;
    const int wm   = wid & 1,  wn   = wid >> 1;   // 2 x 4 warp grid
    const int g    = lane >> 2, tig = lane & 3;

    const float* A  = (MODE == 1) ? g_ao : Ain;
    const float* Ab = A + (size_t)blockIdx.y * 128 * K;
    const float* Wb = W + blockIdx.x * 128;

    const int ar[2]  = { tid & 127, (tid + 256) & 127 };
    const int ac4[2] = { tid >> 7,  (tid + 256) >> 7 };
    const int bk[2]  = { tid >> 5,  (tid + 256) >> 5 };
    const int bn     = (tid & 31) << 2;

    float acc[4][4][4];
    #pragma unroll
    for (int i = 0; i < 4; ++i)
        #pragma unroll
        for (int j = 0; j < 4; ++j)
            #pragma unroll
            for (int r = 0; r < 4; ++r) acc[i][j][r] = 0.0f;

    float4 stA[2], stB[2];
    auto gload = [&](int c) {
        #pragma unroll
        for (int s = 0; s < 2; ++s) {
            stA[s] = *(const float4*)(Ab + (size_t)ar[s] * K + c * 16 + ac4[s] * 4);
            stB[s] = *(const float4*)(Wb + (size_t)(c * 16 + bk[s]) * Nn + bn);
        }
    };
    auto split4 = [&](float4 v, uint4& hi, uint4& lo) {
        hi = make_uint4(f2tf32(v.x), f2tf32(v.y), f2tf32(v.z), f2tf32(v.w));
        lo = make_uint4(f2tf32(v.x - __uint_as_float(hi.x)),
                        f2tf32(v.y - __uint_as_float(hi.y)),
                        f2tf32(v.z - __uint_as_float(hi.z)),
                        f2tf32(v.w - __uint_as_float(hi.w)));
    };
    auto sstore = [&](int b) {
        uint32_t* Ah = sm + b * BUFU;
        uint32_t* Al = Ah + ABUF;
        uint32_t* Bh = Al + ABUF;
        uint32_t* Bl = Bh + BBUF;
        #pragma unroll
        for (int s = 0; s < 2; ++s) {
            uint4 hi, lo;
            split4(stA[s], hi, lo);
            *(uint4*)&Ah[ar[s] * ASTRIDE + ac4[s] * 4] = hi;
            *(uint4*)&Al[ar[s] * ASTRIDE + ac4[s] * 4] = lo;
            split4(stB[s], hi, lo);
            *(uint4*)&Bh[bk[s] * BSTRIDE + bn] = hi;
            *(uint4*)&Bl[bk[s] * BSTRIDE + bn] = lo;
        }
    };

    gload(0);
    sstore(0);
    __syncthreads();

    for (int c = 0; c < NC; ++c) {
        if (c + 1 < NC) gload(c + 1);

        const uint32_t* Ah = sm + (c & 1) * BUFU;
        const uint32_t* Al = Ah + ABUF;
        const uint32_t* Bh = Al + ABUF;
        const uint32_t* Bl = Bh + BBUF;
        #pragma unroll
        for (int ks = 0; ks < 2; ++ks) {
            const int k0 = ks * 8;
            uint32_t afh[4][4], afl[4][4], bfh[4][2], bfl[4][2];
            #pragma unroll
            for (int s = 0; s < 4; ++s) {
                const int m0 = wm * 64 + s * 16;
                const int o0 = (m0 + g)     * ASTRIDE + k0 + tig;
                const int o1 = (m0 + g + 8) * ASTRIDE + k0 + tig;
                afh[s][0] = Ah[o0];     afh[s][1] = Ah[o1];
                afh[s][2] = Ah[o0 + 4]; afh[s][3] = Ah[o1 + 4];
                afl[s][0] = Al[o0];     afl[s][1] = Al[o1];
                afl[s][2] = Al[o0 + 4]; afl[s][3] = Al[o1 + 4];
            }
            #pragma unroll
            for (int s = 0; s < 4; ++s) {
                const int n0 = wn * 32 + s * 8;
                const int p0 = (k0 + tig)     * BSTRIDE + n0 + g;
                const int p1 = (k0 + tig + 4) * BSTRIDE + n0 + g;
                bfh[s][0] = Bh[p0]; bfh[s][1] = Bh[p1];
                bfl[s][0] = Bl[p0]; bfl[s][1] = Bl[p1];
            }
            #pragma unroll
            for (int i = 0; i < 4; ++i)
                #pragma unroll
                for (int j = 0; j < 4; ++j) {
                    mma1688(acc[i][j], afl[i], bfh[j]);   // low-order first
                    mma1688(acc[i][j], afh[i], bfl[j]);
                    mma1688(acc[i][j], afh[i], bfh[j]);
                }
        }

        if (c + 1 < NC) {
            __syncthreads();       // readers of target buffer (iter c-1) done
            sstore((c + 1) & 1);
            __syncthreads();
        }
    }

    // ---- epilogue ----
    #pragma unroll
    for (int i = 0; i < 4; ++i) {
        const int r1 = blockIdx.y * 128 + wm * 64 + i * 16 + g;
        #pragma unroll
        for (int j = 0; j < 4; ++j) {
            const int cgl = blockIdx.x * 128 + wn * 32 + j * 8 + tig * 2;
            if (MODE == 0) {
                const int which = cgl >> 10;
                const int head  = (cgl >> 6) & 15;
                const int dd    = cgl & 63;
                float* base = (which == 0 ? g_q : which == 1 ? g_k : g_v);
                #pragma unroll
                for (int h2 = 0; h2 < 2; ++h2) {
                    const int r = r1 + h2 * 8;
                    const int b = r >> 11, n = r & 2047;
                    float2 v = make_float2(acc[i][j][h2 * 2], acc[i][j][h2 * 2 + 1]);
                    *(float2*)(base + ((size_t)(b * HH + head) * NN + n) * DD + dd) = v;
                }
            } else {
                const float2 bv = *(const float2*)(bias + cgl);
                #pragma unroll
                for (int h2 = 0; h2 < 2; ++h2) {
                    const int r = r1 + h2 * 8;
                    float2 v = make_float2(acc[i][j][h2 * 2] + bv.x,
                                           acc[i][j][h2 * 2 + 1] + bv.y);
                    *(float2*)(Cout + (size_t)r * Nn + cgl) = v;
                }
            }
        }
    }
}

// ===========================================================================
// Per-head LayerNorm over D=64 on q and k; q additionally scaled by sqrt(D)=8.
// ===========================================================================
__global__ __launch_bounds__(128)
void qk_ln_kernel(const float* __restrict__ ln_w, const float* __restrict__ ln_b)
{
    const int R = BB * HH * NN;
    int row  = blockIdx.x * 4 + (threadIdx.x >> 5);
    int lane = threadIdx.x & 31;

    float* base  = (row < R) ? g_q : g_k;
    float  extra = (row < R) ? 8.0f : 1.0f;
    int    r     = (row < R) ? row : (row - R);

    float* p = base + (size_t)r * DD;
    float x0 = p[lane];
    float x1 = p[lane + 32];
    float s  = x0 + x1;
    float ss = x0 * x0 + x1 * x1;
    #pragma unroll
    for (int o = 16; o > 0; o >>= 1) {
        s  += __shfl_xor_sync(0xffffffffu, s,  o);
        ss += __shfl_xor_sync(0xffffffffu, ss, o);
    }
    float mu  = s * (1.0f / 64.0f);
    float var = ss * (1.0f / 64.0f) - mu * mu;
    float inv = rsqrtf(var + 1e-5f);
    p[lane]      = ((x0 - mu) * inv * ln_w[lane]      + ln_b[lane])      * extra;
    p[lane + 32] = ((x1 - mu) * inv * ln_w[lane + 32] + ln_b[lane + 32]) * extra;
}

// ===========================================================================
// Causal flash attention: 128 q-rows x 64-key tiles, 256 threads (16x16),
// per-thread 8 rows x 4 keys.  Conflict-free XOR-swizzled SMEM.
// ===========================================================================
__device__ __forceinline__ int fsw(int r, int c) {
    return (r << 6) + ((((c >> 2) ^ (r >> 2)) & 15) << 2) + (c & 3);
}

__global__ __launch_bounds__(256, 2)
void flash_kernel()
{
    extern __shared__ __align__(1024) float fsm[];
    float* Qs = fsm;            // 128 rows
    float* Ks = fsm + 8192;     // 64 rows
    float* Vs = fsm + 12288;    // 64 rows
    float* Ps = fsm + 16384;    // 128 rows

    const int bh  = blockIdx.y;
    const int qi  = blockIdx.x;
    const int tid = threadIdx.x;
    const int tx  = tid & 15;
    const int ty  = tid >> 4;

    const float* Qg = g_q + (size_t)bh * NN * DD + (size_t)qi * 128 * DD;
    const float* Kg = g_k + (size_t)bh * NN * DD;
    const float* Vg = g_v + (size_t)bh * NN * DD;

    #pragma unroll
    for (int s = 0; s < 8; ++s) {
        int idx = tid + s * 256;
        int r = idx >> 4, c = (idx & 15) << 2;
        *(float4*)&Qs[fsw(r, c)] = *(const float4*)(Qg + r * DD + c);
    }

    float m_i[8], l_i[8], o[8][4];
    #pragma unroll
    for (int i = 0; i < 8; ++i) {
        m_i[i] = -1e30f; l_i[i] = 0.0f;
        #pragma unroll
        for (int j = 0; j < 4; ++j) o[i][j] = 0.0f;
    }

    const int kend = 2 * qi + 1;
    for (int kj = 0; kj <= kend; ++kj) {
        __syncthreads();
        const float* kg = Kg + (size_t)kj * 64 * DD;
        const float* vg = Vg + (size_t)kj * 64 * DD;
        #pragma unroll
        for (int s = 0; s < 4; ++s) {
            int idx = tid + s * 256;
            int r = idx >> 4, c = (idx & 15) << 2;
            *(float4*)&Ks[fsw(r, c)] = *(const float4*)(kg + r * DD + c);
            *(float4*)&Vs[fsw(r, c)] = *(const float4*)(vg + r * DD + c);
        }
        __syncthreads();

        float s4[8][4];
        #pragma unroll
        for (int i = 0; i < 8; ++i)
            #pragma unroll
            for (int j = 0; j < 4; ++j) s4[i][j] = 0.0f;

        #pragma unroll
        for (int k4 = 0; k4 < 64; k4 += 4) {
            float4 bf[4];
            #pragma unroll
            for (int j = 0; j < 4; ++j)
                bf[j] = *(float4*)&Ks[fsw(tx * 4 + j, k4)];
            #pragma unroll
            for (int i = 0; i < 8; ++i) {
                float4 af = *(float4*)&Qs[fsw(ty * 8 + i, k4)];
                #pragma unroll
                for (int j = 0; j < 4; ++j) {
                    s4[i][j] = fmaf(af.x, bf[j].x, s4[i][j]);
                    s4[i][j] = fmaf(af.y, bf[j].y, s4[i][j]);
                    s4[i][j] = fmaf(af.z, bf[j].z, s4[i][j]);
                    s4[i][j] = fmaf(af.w, bf[j].w, s4[i][j]);
                }
            }
        }

        if (kj >= 2 * qi) {
            #pragma unroll
            for (int i = 0; i < 8; ++i)
                #pragma unroll
                for (int j = 0; j < 4; ++j)
                    if (qi * 128 + ty * 8 + i < kj * 64 + tx * 4 + j)
                        s4[i][j] = -1e30f;
        }

        #pragma unroll
        for (int i = 0; i < 8; ++i) {
            float mx = fmaxf(fmaxf(s4[i][0], s4[i][1]), fmaxf(s4[i][2], s4[i][3]));
            #pragma unroll
            for (int off = 8; off > 0; off >>= 1)
                mx = fmaxf(mx, __shfl_xor_sync(0xffffffffu, mx, off));
            float mnew  = fmaxf(m_i[i], mx);
            float alpha = __expf(m_i[i] - mnew);
            m_i[i] = mnew;
            float rs = 0.0f;
            #pragma unroll
            for (int j = 0; j < 4; ++j) {
                float pv = __expf(s4[i][j] - mnew);
                s4[i][j] = pv;
                rs += pv;
            }
            #pragma unroll
            for (int off = 8; off > 0; off >>= 1)
                rs += __shfl_xor_sync(0xffffffffu, rs, off);
            l_i[i] = l_i[i] * alpha + rs;
            #pragma unroll
            for (int j = 0; j < 4; ++j) o[i][j] *= alpha;
            *(float4*)&Ps[fsw(ty * 8 + i, tx * 4)] =
                make_float4(s4[i][0], s4[i][1], s4[i][2], s4[i][3]);
        }
        __syncthreads();

        #pragma unroll
        for (int k4 = 0; k4 < 64; k4 += 4) {
            float4 v0 = *(float4*)&Vs[fsw(k4 + 0, tx * 4)];
            float4 v1 = *(float4*)&Vs[fsw(k4 + 1, tx * 4)];
            float4 v2 = *(float4*)&Vs[fsw(k4 + 2, tx * 4)];
            float4 v3 = *(float4*)&Vs[fsw(k4 + 3, tx * 4)];
            #pragma unroll
            for (int i = 0; i < 8; ++i) {
                float4 pf = *(float4*)&Ps[fsw(ty * 8 + i, k4)];
                o[i][0] = fmaf(pf.x, v0.x, o[i][0]);
                o[i][1] = fmaf(pf.x, v0.y, o[i][1]);
                o[i][2] = fmaf(pf.x, v0.z, o[i][2]);
                o[i][3] = fmaf(pf.x, v0.w, o[i][3]);
                o[i][0] = fmaf(pf.y, v1.x, o[i][0]);
                o[i][1] = fmaf(pf.y, v1.y, o[i][1]);
                o[i][2] = fmaf(pf.y, v1.z, o[i][2]);
                o[i][3] = fmaf(pf.y, v1.w, o[i][3]);
                o[i][0] = fmaf(pf.z, v2.x, o[i][0]);
                o[i][1] = fmaf(pf.z, v2.y, o[i][1]);
                o[i][2] = fmaf(pf.z, v2.z, o[i][2]);
                o[i][3] = fmaf(pf.z, v2.w, o[i][3]);
                o[i][0] = fmaf(pf.w, v3.x, o[i][0]);
                o[i][1] = fmaf(pf.w, v3.y, o[i][1]);
                o[i][2] = fmaf(pf.w, v3.z, o[i][2]);
                o[i][3] = fmaf(pf.w, v3.w, o[i][3]);
            }
        }
    }

    const int b = bh >> 4;
    const int h = bh & 15;
    #pragma unroll
    for (int i = 0; i < 8; ++i) {
        float inv = 1.0f / l_i[i];
        int n = qi * 128 + ty * 8 + i;
        size_t off = (((size_t)b * NN + n) * HH + h) * DD + tx * 4;
        *(float4*)&g_ao[off] = make_float4(o[i][0] * inv, o[i][1] * inv,
                                           o[i][2] * inv, o[i][3] * inv);
    }
}

// ===========================================================================
extern "C" void kernel_launch(void* const* d_in, const int* in_sizes, int n_in,
                              void* d_out, int out_size)
{
    const float* x      = (const float*)d_in[0];
    const float* w_qkv  = (const float*)d_in[1];
    const float* w_proj = (const float*)d_in[2];
    const float* b_proj = (const float*)d_in[3];
    const float* ln_w   = (const float*)d_in[4];
    const float* ln_b   = (const float*)d_in[5];
    float* out = (float*)d_out;

    cudaFuncSetAttribute(tc_gemm<0>, cudaFuncAttributeMaxDynamicSharedMemorySize, GEMM_SMEM);
    cudaFuncSetAttribute(tc_gemm<1>, cudaFuncAttributeMaxDynamicSharedMemorySize, GEMM_SMEM);
    cudaFuncSetAttribute(flash_kernel, cudaFuncAttributeMaxDynamicSharedMemorySize, 98304);

    // 1) QKV projection (3xTF32 mma.sync) + scatter to [B,H,N,D]
    tc_gemm<0><<<dim3(24, 32), 256, GEMM_SMEM>>>(x, w_qkv, nullptr, nullptr);

    // 2) per-head LayerNorm on q,k (+ sqrt(D) folded into q)
    qk_ln_kernel<<<(2 * BB * HH * NN) / 4, 128>>>(ln_w, ln_b);

    // 3) causal flash attention
    flash_kernel<<<dim3(NN / 128, BB * HH), 256, 98304>>>();

    // 4) output projection + bias (3xTF32 mma.sync)
    tc_gemm<1><<<dim3(8, 32), 256, GEMM_SMEM>>>(nullptr, w_proj, b_proj, out);
}

// round 5
// speedup vs baseline: 1.6504x; 1.6066x over previous
#include <cuda_runtime.h>
#include <cuda_fp16.h>
#include <math.h>
#include <stdint.h>

#define BB 2
#define NN 2048
#define CC 1024
#define HH 16
#define DD 64

// Scratch (device globals: allocation-free per harness rules)
__device__ float g_q[BB*HH*NN*DD];    // [B,H,N,D]
__device__ float g_k[BB*HH*NN*DD];
__device__ float g_v[BB*HH*NN*DD];
__device__ float g_ao[BB*NN*CC];      // [B,N,(H D)] attention output

// ===========================================================================
// helpers
// ===========================================================================
__device__ __forceinline__ uint32_t f2tf32(float x) {
    uint32_t r;
    asm("cvt.rna.tf32.f32 %0, %1;" : "=r"(r) : "f"(x));
    return r;
}
__device__ __forceinline__ void mma1688(float* d, const uint32_t* a, const uint32_t* b) {
    asm volatile(
        "mma.sync.aligned.m16n8k8.row.col.f32.tf32.tf32.f32 "
        "{%0,%1,%2,%3}, {%4,%5,%6,%7}, {%8,%9}, {%0,%1,%2,%3};"
        : "+f"(d[0]), "+f"(d[1]), "+f"(d[2]), "+f"(d[3])
        : "r"(a[0]), "r"(a[1]), "r"(a[2]), "r"(a[3]), "r"(b[0]), "r"(b[1]));
}
__device__ __forceinline__ void mma16816(float* d, const uint32_t* a,
                                         uint32_t b0, uint32_t b1) {
    asm volatile(
        "mma.sync.aligned.m16n8k16.row.col.f32.f16.f16.f32 "
        "{%0,%1,%2,%3}, {%4,%5,%6,%7}, {%8,%9}, {%0,%1,%2,%3};"
        : "+f"(d[0]), "+f"(d[1]), "+f"(d[2]), "+f"(d[3])
        : "r"(a[0]), "r"(a[1]), "r"(a[2]), "r"(a[3]), "r"(b0), "r"(b1));
}
__device__ __forceinline__ uint32_t smem_u32(const void* p) {
    uint32_t a;
    asm("{ .reg .u64 t; cvta.to.shared.u64 t, %1; cvt.u32.u64 %0, t; }"
        : "=r"(a) : "l"(p));
    return a;
}
#define LDSM_X4_T(r0, r1, r2, r3, addr) \
    asm volatile("ldmatrix.sync.aligned.m8n8.x4.trans.shared.b16 " \
                 "{%0,%1,%2,%3}, [%4];" \
                 : "=r"(r0), "=r"(r1), "=r"(r2), "=r"(r3) : "r"(addr))

__device__ __forceinline__ uint32_t packh2(float a, float b) {
    __half2 h = __floats2half2_rn(a, b);
    return *(uint32_t*)&h;
}

// ===========================================================================
// 3xTF32 mma.sync GEMM:  C[4096 x Nn] = A[4096 x 1024] @ W[1024 x Nn]
// CTA 128x128, BK=16 double-buffered (1 sync/chunk). 8 warps 2(m) x 4(n).
// MODE 0: A=x, W=w_qkv (Nn=3072), scatter epilogue -> g_q/g_k/g_v [B,H,N,D]
// MODE 1: A=g_ao, W=w_proj (Nn=1024), +bias -> Cout
// ===========================================================================
#define ASTRIDE 20
#define BSTRIDE 136
#define ABUF (128 * ASTRIDE)
#define BBUF (16 * BSTRIDE)
#define BUFU (2 * ABUF + 2 * BBUF)
#define GEMM_SMEM (2 * BUFU * 4)

template<int MODE>
__global__ __launch_bounds__(256)
void tc_gemm(const float* __restrict__ Ain, const float* __restrict__ W,
             const float* __restrict__ bias, float* __restrict__ Cout)
{
    constexpr int K  = 1024;
    constexpr int NC = K / 16;
    constexpr int Nn = (MODE == 0) ? 3072 : 1024;

    extern __shared__ uint32_t sm[];

    const int tid  = threadIdx.x;
    const int wid  = tid >> 5, lane = tid & 31;
    const int wm   = wid & 1,  wn   = wid >> 1;
    const int g    = lane >> 2, tig = lane & 3;

    const float* A  = (MODE == 1) ? g_ao : Ain;
    const float* Ab = A + (size_t)blockIdx.y * 128 * K;
    const float* Wb = W + blockIdx.x * 128;

    const int ar[2]  = { tid & 127, (tid + 256) & 127 };
    const int ac4[2] = { tid >> 7,  (tid + 256) >> 7 };
    const int bk[2]  = { tid >> 5,  (tid + 256) >> 5 };
    const int bn     = (tid & 31) << 2;

    float acc[4][4][4];
    #pragma unroll
    for (int i = 0; i < 4; ++i)
        #pragma unroll
        for (int j = 0; j < 4; ++j)
            #pragma unroll
            for (int r = 0; r < 4; ++r) acc[i][j][r] = 0.0f;

    float4 stA[2], stB[2];
    auto gload = [&](int c) {
        #pragma unroll
        for (int s = 0; s < 2; ++s) {
            stA[s] = *(const float4*)(Ab + (size_t)ar[s] * K + c * 16 + ac4[s] * 4);
            stB[s] = *(const float4*)(Wb + (size_t)(c * 16 + bk[s]) * Nn + bn);
        }
    };
    auto split4 = [&](float4 v, uint4& hi, uint4& lo) {
        hi = make_uint4(f2tf32(v.x), f2tf32(v.y), f2tf32(v.z), f2tf32(v.w));
        lo = make_uint4(f2tf32(v.x - __uint_as_float(hi.x)),
                        f2tf32(v.y - __uint_as_float(hi.y)),
                        f2tf32(v.z - __uint_as_float(hi.z)),
                        f2tf32(v.w - __uint_as_float(hi.w)));
    };
    auto sstore = [&](int b) {
        uint32_t* Ah = sm + b * BUFU;
        uint32_t* Al = Ah + ABUF;
        uint32_t* Bh = Al + ABUF;
        uint32_t* Bl = Bh + BBUF;
        #pragma unroll
        for (int s = 0; s < 2; ++s) {
            uint4 hi, lo;
            split4(stA[s], hi, lo);
            *(uint4*)&Ah[ar[s] * ASTRIDE + ac4[s] * 4] = hi;
            *(uint4*)&Al[ar[s] * ASTRIDE + ac4[s] * 4] = lo;
            split4(stB[s], hi, lo);
            *(uint4*)&Bh[bk[s] * BSTRIDE + bn] = hi;
            *(uint4*)&Bl[bk[s] * BSTRIDE + bn] = lo;
        }
    };

    gload(0);
    sstore(0);
    __syncthreads();

    for (int c = 0; c < NC; ++c) {
        if (c + 1 < NC) gload(c + 1);

        const uint32_t* Ah = sm + (c & 1) * BUFU;
        const uint32_t* Al = Ah + ABUF;
        const uint32_t* Bh = Al + ABUF;
        const uint32_t* Bl = Bh + BBUF;
        #pragma unroll
        for (int ks = 0; ks < 2; ++ks) {
            const int k0 = ks * 8;
            uint32_t afh[4][4], afl[4][4], bfh[4][2], bfl[4][2];
            #pragma unroll
            for (int s = 0; s < 4; ++s) {
                const int m0 = wm * 64 + s * 16;
                const int o0 = (m0 + g)     * ASTRIDE + k0 + tig;
                const int o1 = (m0 + g + 8) * ASTRIDE + k0 + tig;
                afh[s][0] = Ah[o0];     afh[s][1] = Ah[o1];
                afh[s][2] = Ah[o0 + 4]; afh[s][3] = Ah[o1 + 4];
                afl[s][0] = Al[o0];     afl[s][1] = Al[o1];
                afl[s][2] = Al[o0 + 4]; afl[s][3] = Al[o1 + 4];
            }
            #pragma unroll
            for (int s = 0; s < 4; ++s) {
                const int n0 = wn * 32 + s * 8;
                const int p0 = (k0 + tig)     * BSTRIDE + n0 + g;
                const int p1 = (k0 + tig + 4) * BSTRIDE + n0 + g;
                bfh[s][0] = Bh[p0]; bfh[s][1] = Bh[p1];
                bfl[s][0] = Bl[p0]; bfl[s][1] = Bl[p1];
            }
            #pragma unroll
            for (int i = 0; i < 4; ++i)
                #pragma unroll
                for (int j = 0; j < 4; ++j) {
                    mma1688(acc[i][j], afl[i], bfh[j]);
                    mma1688(acc[i][j], afh[i], bfl[j]);
                    mma1688(acc[i][j], afh[i], bfh[j]);
                }
        }

        if (c + 1 < NC) {
            sstore((c + 1) & 1);
            __syncthreads();
        }
    }

    // ---- epilogue ----
    #pragma unroll
    for (int i = 0; i < 4; ++i) {
        const int r1 = blockIdx.y * 128 + wm * 64 + i * 16 + g;
        #pragma unroll
        for (int j = 0; j < 4; ++j) {
            const int cgl = blockIdx.x * 128 + wn * 32 + j * 8 + tig * 2;
            if (MODE == 0) {
                const int which = cgl >> 10;
                const int head  = (cgl >> 6) & 15;
                const int dd    = cgl & 63;
                float* base = (which == 0 ? g_q : which == 1 ? g_k : g_v);
                #pragma unroll
                for (int h2 = 0; h2 < 2; ++h2) {
                    const int r = r1 + h2 * 8;
                    const int b = r >> 11, n = r & 2047;
                    float2 v = make_float2(acc[i][j][h2 * 2], acc[i][j][h2 * 2 + 1]);
                    *(float2*)(base + ((size_t)(b * HH + head) * NN + n) * DD + dd) = v;
                }
            } else {
                const float2 bv = *(const float2*)(bias + cgl);
                #pragma unroll
                for (int h2 = 0; h2 < 2; ++h2) {
                    const int r = r1 + h2 * 8;
                    float2 v = make_float2(acc[i][j][h2 * 2] + bv.x,
                                           acc[i][j][h2 * 2 + 1] + bv.y);
                    *(float2*)(Cout + (size_t)r * Nn + cgl) = v;
                }
            }
        }
    }
}

// ===========================================================================
// Per-head LayerNorm over D=64 on q and k; q additionally scaled by sqrt(D)=8.
// ===========================================================================
__global__ __launch_bounds__(128)
void qk_ln_kernel(const float* __restrict__ ln_w, const float* __restrict__ ln_b)
{
    const int R = BB * HH * NN;
    int row  = blockIdx.x * 4 + (threadIdx.x >> 5);
    int lane = threadIdx.x & 31;

    float* base  = (row < R) ? g_q : g_k;
    float  extra = (row < R) ? 8.0f : 1.0f;
    int    r     = (row < R) ? row : (row - R);

    float* p = base + (size_t)r * DD;
    float x0 = p[lane];
    float x1 = p[lane + 32];
    float s  = x0 + x1;
    float ss = x0 * x0 + x1 * x1;
    #pragma unroll
    for (int o = 16; o > 0; o >>= 1) {
        s  += __shfl_xor_sync(0xffffffffu, s,  o);
        ss += __shfl_xor_sync(0xffffffffu, ss, o);
    }
    float mu  = s * (1.0f / 64.0f);
    float var = ss * (1.0f / 64.0f) - mu * mu;
    float inv = rsqrtf(var + 1e-5f);
    p[lane]      = ((x0 - mu) * inv * ln_w[lane]      + ln_b[lane])      * extra;
    p[lane + 32] = ((x1 - mu) * inv * ln_w[lane + 32] + ln_b[lane + 32]) * extra;
}

// ===========================================================================
// Tensor-core causal flash attention.
// CTA: 128 q-rows x one (b,h); 8 warps x 16 rows each; key tiles of 64.
// S = QK^T: 3xTF32 m16n8k8 (Q frags hi/lo in regs; K hi/lo in SMEM [key][d],
//           b-frag indexing transposes: bank-conflict-free at stride 68).
// P.V: 3-term fp16 m16n8k16 (P hi/lo packed from S c-frags; V hi/lo fp16 in
//      SMEM [key][d] stride 72, fragments via ldmatrix.x4.trans).
// ===========================================================================
#define KSTR 68      // K smem stride (floats)
#define VSTR 72      // V smem stride (halves)
#define FL_SMEM (2*64*KSTR*4 + 2*64*VSTR*2)   // 34816 + 18432 = 53248 B

__global__ __launch_bounds__(256, 1)
void flash_mma()
{
    extern __shared__ __align__(1024) char fsm[];
    float*  Khi = (float*)fsm;                   // [64][KSTR]
    float*  Klo = Khi + 64 * KSTR;
    __half* Vhi = (__half*)(Klo + 64 * KSTR);    // [64][VSTR]
    __half* Vlo = Vhi + 64 * VSTR;
    float*  Qst = (float*)fsm;                   // staging alias (used first)
    const uint32_t* KhiU = (const uint32_t*)Khi;
    const uint32_t* KloU = (const uint32_t*)Klo;

    const int bh  = blockIdx.y;
    const int qi  = blockIdx.x;
    const int tid = threadIdx.x;
    const int wid = tid >> 5, lane = tid & 31;
    const int g   = lane >> 2, tig = lane & 3;

    const float* Qg = g_q + (size_t)bh * NN * DD + (size_t)qi * 128 * DD;
    const float* Kg = g_k + (size_t)bh * NN * DD;
    const float* Vg = g_v + (size_t)bh * NN * DD;

    // ---- stage Q, then extract per-warp a-frags (hi/lo) into registers ----
    #pragma unroll
    for (int s = 0; s < 8; ++s) {
        int idx = tid + s * 256;
        int r = idx >> 4, c = (idx & 15) << 2;
        *(float4*)&Qst[r * KSTR + c] = *(const float4*)(Qg + r * DD + c);
    }
    __syncthreads();

    uint32_t qh[8][4], ql[8][4];
    {
        const int r0 = (wid * 16 + g) * KSTR;
        const int r1 = (wid * 16 + g + 8) * KSTR;
        #pragma unroll
        for (int kk = 0; kk < 8; ++kk) {
            float v0 = Qst[r0 + kk * 8 + tig];
            float v1 = Qst[r1 + kk * 8 + tig];
            float v2 = Qst[r0 + kk * 8 + tig + 4];
            float v3 = Qst[r1 + kk * 8 + tig + 4];
            qh[kk][0] = f2tf32(v0); ql[kk][0] = f2tf32(v0 - __uint_as_float(qh[kk][0]));
            qh[kk][1] = f2tf32(v1); ql[kk][1] = f2tf32(v1 - __uint_as_float(qh[kk][1]));
            qh[kk][2] = f2tf32(v2); ql[kk][2] = f2tf32(v2 - __uint_as_float(qh[kk][2]));
            qh[kk][3] = f2tf32(v3); ql[kk][3] = f2tf32(v3 - __uint_as_float(qh[kk][3]));
        }
    }

    float m0 = -1e30f, m1 = -1e30f, l0 = 0.0f, l1 = 0.0f;
    float o[8][4];
    #pragma unroll
    for (int j = 0; j < 8; ++j)
        #pragma unroll
        for (int r = 0; r < 4; ++r) o[j][r] = 0.0f;

    const uint32_t vhiB = smem_u32(Vhi);
    const uint32_t vloB = smem_u32(Vlo);
    const int kend = 2 * qi + 1;

    for (int kj = 0; kj <= kend; ++kj) {
        __syncthreads();                 // prior-tile consumers done (covers Q too)
        // ---- load K (tf32 hi/lo fp32) and V (fp16 hi/lo) ----
        const float* kg = Kg + (size_t)kj * 64 * DD;
        const float* vg = Vg + (size_t)kj * 64 * DD;
        #pragma unroll
        for (int s = 0; s < 4; ++s) {
            int idx = tid + s * 256;
            int key = idx >> 4, c = (idx & 15) << 2;
            float4 kv = *(const float4*)(kg + key * DD + c);
            uint4 hi, lo;
            hi = make_uint4(f2tf32(kv.x), f2tf32(kv.y), f2tf32(kv.z), f2tf32(kv.w));
            lo = make_uint4(f2tf32(kv.x - __uint_as_float(hi.x)),
                            f2tf32(kv.y - __uint_as_float(hi.y)),
                            f2tf32(kv.z - __uint_as_float(hi.z)),
                            f2tf32(kv.w - __uint_as_float(hi.w)));
            *(uint4*)&Khi[key * KSTR + c] = hi;
            *(uint4*)&Klo[key * KSTR + c] = lo;

            float4 vv = *(const float4*)(vg + key * DD + c);
            __half2 h01 = __floats2half2_rn(vv.x, vv.y);
            __half2 h23 = __floats2half2_rn(vv.z, vv.w);
            float2 f01 = __half22float2(h01);
            float2 f23 = __half22float2(h23);
            __half2 l01 = __floats2half2_rn(vv.x - f01.x, vv.y - f01.y);
            __half2 l23 = __floats2half2_rn(vv.z - f23.x, vv.w - f23.y);
            *(__half2*)&Vhi[key * VSTR + c]     = h01;
            *(__half2*)&Vhi[key * VSTR + c + 2] = h23;
            *(__half2*)&Vlo[key * VSTR + c]     = l01;
            *(__half2*)&Vlo[key * VSTR + c + 2] = l23;
        }
        __syncthreads();

        // ---- S = Q K^T (3xTF32) ----
        float sf[8][4];
        #pragma unroll
        for (int j = 0; j < 8; ++j)
            #pragma unroll
            for (int r = 0; r < 4; ++r) sf[j][r] = 0.0f;

        #pragma unroll
        for (int kk = 0; kk < 8; ++kk) {
            #pragma unroll
            for (int j = 0; j < 8; ++j) {
                const int ro = (j * 8 + g) * KSTR + kk * 8 + tig;
                uint32_t bhf[2] = { KhiU[ro], KhiU[ro + 4] };
                uint32_t blf[2] = { KloU[ro], KloU[ro + 4] };
                mma1688(sf[j], ql[kk], bhf);
                mma1688(sf[j], qh[kk], blf);
                mma1688(sf[j], qh[kk], bhf);
            }
        }

        // ---- causal mask on diagonal tiles ----
        if (kj >= 2 * qi) {
            const int row0 = qi * 128 + wid * 16 + g;
            const int row1 = row0 + 8;
            #pragma unroll
            for (int j = 0; j < 8; ++j) {
                const int c0 = kj * 64 + j * 8 + tig * 2;
                if (row0 < c0)     sf[j][0] = -1e30f;
                if (row0 < c0 + 1) sf[j][1] = -1e30f;
                if (row1 < c0)     sf[j][2] = -1e30f;
                if (row1 < c0 + 1) sf[j][3] = -1e30f;
            }
        }

        // ---- online softmax (rows g, g+8; quad-replicated over tig) ----
        float mx0 = -1e30f, mx1 = -1e30f;
        #pragma unroll
        for (int j = 0; j < 8; ++j) {
            mx0 = fmaxf(mx0, fmaxf(sf[j][0], sf[j][1]));
            mx1 = fmaxf(mx1, fmaxf(sf[j][2], sf[j][3]));
        }
        mx0 = fmaxf(mx0, __shfl_xor_sync(0xffffffffu, mx0, 1));
        mx0 = fmaxf(mx0, __shfl_xor_sync(0xffffffffu, mx0, 2));
        mx1 = fmaxf(mx1, __shfl_xor_sync(0xffffffffu, mx1, 1));
        mx1 = fmaxf(mx1, __shfl_xor_sync(0xffffffffu, mx1, 2));
        float mn0 = fmaxf(m0, mx0), mn1 = fmaxf(m1, mx1);
        float a0 = __expf(m0 - mn0), a1 = __expf(m1 - mn1);
        m0 = mn0; m1 = mn1;
        float rs0 = 0.0f, rs1 = 0.0f;
        #pragma unroll
        for (int j = 0; j < 8; ++j) {
            sf[j][0] = __expf(sf[j][0] - mn0); rs0 += sf[j][0];
            sf[j][1] = __expf(sf[j][1] - mn0); rs0 += sf[j][1];
            sf[j][2] = __expf(sf[j][2] - mn1); rs1 += sf[j][2];
            sf[j][3] = __expf(sf[j][3] - mn1); rs1 += sf[j][3];
        }
        rs0 += __shfl_xor_sync(0xffffffffu, rs0, 1);
        rs0 += __shfl_xor_sync(0xffffffffu, rs0, 2);
        rs1 += __shfl_xor_sync(0xffffffffu, rs1, 1);
        rs1 += __shfl_xor_sync(0xffffffffu, rs1, 2);
        l0 = l0 * a0 + rs0;
        l1 = l1 * a1 + rs1;
        #pragma unroll
        for (int j = 0; j < 8; ++j) {
            o[j][0] *= a0; o[j][1] *= a0;
            o[j][2] *= a1; o[j][3] *= a1;
        }

        // ---- P fragments (fp16 hi + lo) from S c-frags ----
        uint32_t ph[4][4], pl[4][4];
        #pragma unroll
        for (int t = 0; t < 4; ++t) {
            const int j0 = 2 * t, j1 = 2 * t + 1;
            float v00 = sf[j0][0], v01 = sf[j0][1], v02 = sf[j0][2], v03 = sf[j0][3];
            float v10 = sf[j1][0], v11 = sf[j1][1], v12 = sf[j1][2], v13 = sf[j1][3];
            ph[t][0] = packh2(v00, v01);
            ph[t][1] = packh2(v02, v03);
            ph[t][2] = packh2(v10, v11);
            ph[t][3] = packh2(v12, v13);
            float2 f0 = __half22float2(*(__half2*)&ph[t][0]);
            float2 f1 = __half22float2(*(__half2*)&ph[t][1]);
            float2 f2 = __half22float2(*(__half2*)&ph[t][2]);
            float2 f3 = __half22float2(*(__half2*)&ph[t][3]);
            pl[t][0] = packh2(v00 - f0.x, v01 - f0.y);
            pl[t][1] = packh2(v02 - f1.x, v03 - f1.y);
            pl[t][2] = packh2(v10 - f2.x, v11 - f2.y);
            pl[t][3] = packh2(v12 - f3.x, v13 - f3.y);
        }

        // ---- O += P V  (fp16 3-term, V frags via ldmatrix.x4.trans) ----
        #pragma unroll
        for (int t = 0; t < 4; ++t) {
            #pragma unroll
            for (int jp = 0; jp < 4; ++jp) {
                const int row = t * 16 + ((lane >> 3) & 1) * 8 + (lane & 7);
                const int col = jp * 16 + (lane >> 4) * 8;
                const uint32_t off = (uint32_t)(row * VSTR + col) * 2;
                uint32_t h0, h1, h2, h3, e0, e1, e2, e3;
                LDSM_X4_T(h0, h1, h2, h3, vhiB + off);
                LDSM_X4_T(e0, e1, e2, e3, vloB + off);
                mma16816(o[2 * jp],     pl[t], h0, h1);
                mma16816(o[2 * jp],     ph[t], e0, e1);
                mma16816(o[2 * jp],     ph[t], h0, h1);
                mma16816(o[2 * jp + 1], pl[t], h2, h3);
                mma16816(o[2 * jp + 1], ph[t], e2, e3);
                mma16816(o[2 * jp + 1], ph[t], h2, h3);
            }
        }
    }

    // ---- finalize, scatter to [B,N,H,D] ----
    const int b = bh >> 4;
    const int h = bh & 15;
    const float inv0 = 1.0f / l0, inv1 = 1.0f / l1;
    const int n0 = qi * 128 + wid * 16 + g;
    const int n1 = n0 + 8;
    #pragma unroll
    for (int j = 0; j < 8; ++j) {
        const int d = j * 8 + tig * 2;
        *(float2*)(g_ao + (((size_t)b * NN + n0) * HH + h) * DD + d) =
            make_float2(o[j][0] * inv0, o[j][1] * inv0);
        *(float2*)(g_ao + (((size_t)b * NN + n1) * HH + h) * DD + d) =
            make_float2(o[j][2] * inv1, o[j][3] * inv1);
    }
}

// ===========================================================================
extern "C" void kernel_launch(void* const* d_in, const int* in_sizes, int n_in,
                              void* d_out, int out_size)
{
    const float* x      = (const float*)d_in[0];
    const float* w_qkv  = (const float*)d_in[1];
    const float* w_proj = (const float*)d_in[2];
    const float* b_proj = (const float*)d_in[3];
    const float* ln_w   = (const float*)d_in[4];
    const float* ln_b   = (const float*)d_in[5];
    float* out = (float*)d_out;

    cudaFuncSetAttribute(tc_gemm<0>, cudaFuncAttributeMaxDynamicSharedMemorySize, GEMM_SMEM);
    cudaFuncSetAttribute(tc_gemm<1>, cudaFuncAttributeMaxDynamicSharedMemorySize, GEMM_SMEM);
    cudaFuncSetAttribute(flash_mma, cudaFuncAttributeMaxDynamicSharedMemorySize, FL_SMEM);

    // 1) QKV projection (3xTF32 mma.sync) + scatter to [B,H,N,D]
    tc_gemm<0><<<dim3(24, 32), 256, GEMM_SMEM>>>(x, w_qkv, nullptr, nullptr);

    // 2) per-head LayerNorm on q,k (+ sqrt(D) folded into q)
    qk_ln_kernel<<<(2 * BB * HH * NN) / 4, 128>>>(ln_w, ln_b);

    // 3) tensor-core causal flash attention
    flash_mma<<<dim3(NN / 128, BB * HH), 256, FL_SMEM>>>();

    // 4) output projection + bias (3xTF32 mma.sync)
    tc_gemm<1><<<dim3(8, 32), 256, GEMM_SMEM>>>(nullptr, w_proj, b_proj, out);
}

// round 7
// speedup vs baseline: 2.6785x; 1.6229x over previous
#include <cuda_runtime.h>
#include <cuda_fp16.h>
#include <math.h>
#include <stdint.h>

#define BB 2
#define NN 2048
#define CC 1024
#define HH 16
#define DD 64

// Scratch (device globals: allocation-free per harness rules)
__device__ float g_q[BB*HH*NN*DD];    // [B,H,N,D]
__device__ float g_k[BB*HH*NN*DD];
__device__ float g_v[BB*HH*NN*DD];
__device__ float g_ao[BB*NN*CC];      // [B,N,(H D)] attention output

// ===========================================================================
// helpers
// ===========================================================================
__device__ __forceinline__ void mma16816(float* d, const uint32_t* a,
                                         uint32_t b0, uint32_t b1) {
    asm volatile(
        "mma.sync.aligned.m16n8k16.row.col.f32.f16.f16.f32 "
        "{%0,%1,%2,%3}, {%4,%5,%6,%7}, {%8,%9}, {%0,%1,%2,%3};"
        : "+f"(d[0]), "+f"(d[1]), "+f"(d[2]), "+f"(d[3])
        : "r"(a[0]), "r"(a[1]), "r"(a[2]), "r"(a[3]), "r"(b0), "r"(b1));
}
__device__ __forceinline__ uint32_t smem_u32(const void* p) {
    uint32_t a;
    asm("{ .reg .u64 t; cvta.to.shared.u64 t, %1; cvt.u32.u64 %0, t; }"
        : "=r"(a) : "l"(p));
    return a;
}
#define LDSM_X4(r0, r1, r2, r3, addr) \
    asm volatile("ldmatrix.sync.aligned.m8n8.x4.shared.b16 " \
                 "{%0,%1,%2,%3}, [%4];" \
                 : "=r"(r0), "=r"(r1), "=r"(r2), "=r"(r3) : "r"(addr))
#define LDSM_X4_T(r0, r1, r2, r3, addr) \
    asm volatile("ldmatrix.sync.aligned.m8n8.x4.trans.shared.b16 " \
                 "{%0,%1,%2,%3}, [%4];" \
                 : "=r"(r0), "=r"(r1), "=r"(r2), "=r"(r3) : "r"(addr))

__device__ __forceinline__ uint32_t packh2(float a, float b) {
    __half2 h = __floats2half2_rn(a, b);
    return *(uint32_t*)&h;
}
// split (a,b) into fp16 hi pair + fp16 residual pair
__device__ __forceinline__ void splitp(float a, float b, uint32_t& hi, uint32_t& lo) {
    __half2 h = __floats2half2_rn(a, b);
    float2 f = __half22float2(h);
    __half2 l = __floats2half2_rn(a - f.x, b - f.y);
    hi = *(uint32_t*)&h;
    lo = *(uint32_t*)&l;
}
// split float4 into 4 hi halves (uint2) + 4 lo halves (uint2)
__device__ __forceinline__ void split8(float4 v, uint2& hi, uint2& lo) {
    splitp(v.x, v.y, hi.x, lo.x);
    splitp(v.z, v.w, hi.y, lo.y);
}

// ===========================================================================
// fp16 3-term mma.sync GEMM:  C[4096 x Nn] = A[4096 x 1024] @ W[1024 x Nn]
// CTA 128x128, BK=16 double-buffered, 1 sync/chunk. 8 warps 2(m) x 4(n).
// Operands split hi/lo fp16; acc += al*bh + ah*bl + ah*bh (products exact,
// only al*bl ~2^-21 dropped).  Fragments via ldmatrix (A) / ldmatrix.trans (B).
// MODE 0: A=x, W=w_qkv (Nn=3072), scatter epilogue -> g_q/g_k/g_v [B,H,N,D]
// MODE 1: A=g_ao, W=w_proj (Nn=1024), +bias -> Cout
// ===========================================================================
#define GASTR 24                    // A smem stride (halves): ldmatrix conflict-free
#define GBSTR 136                   // B smem stride (halves): ldmatrix.trans conflict-free
#define GSA (128 * GASTR)           // 3072 halves
#define GSB (16 * GBSTR)            // 2176 halves
#define GSTG (2 * (GSA + GSB))      // 10496 halves per stage
#define GEMM_SMEM (2 * GSTG * 2)    // 41984 B

template<int MODE>
__global__ __launch_bounds__(256)
void tc_gemm(const float* __restrict__ Ain, const float* __restrict__ W,
             const float* __restrict__ bias, float* __restrict__ Cout)
{
    constexpr int K  = 1024;
    constexpr int NC = K / 16;
    constexpr int Nn = (MODE == 0) ? 3072 : 1024;

    extern __shared__ __half smh[];

    const int tid  = threadIdx.x;
    const int wid  = tid >> 5, lane = tid & 31;
    const int wm   = wid & 1,  wn   = wid >> 1;
    const int g    = lane >> 2, tig = lane & 3;

    const float* A  = (MODE == 1) ? g_ao : Ain;
    const float* Ab = A + (size_t)blockIdx.y * 128 * K;
    const float* Wb = W + blockIdx.x * 128;

    // per-thread gmem coords: A 2 float4 (128x16), B 2 float4 (16x128)
    const int arA[2] = { tid >> 2, (tid + 256) >> 2 };
    const int acA[2] = { (tid & 3) << 2, (tid & 3) << 2 };
    const int kB[2]  = { tid >> 5, (tid + 256) >> 5 };
    const int nB     = (tid & 31) << 2;

    float acc[4][4][4];
    #pragma unroll
    for (int i = 0; i < 4; ++i)
        #pragma unroll
        for (int j = 0; j < 4; ++j)
            #pragma unroll
            for (int r = 0; r < 4; ++r) acc[i][j][r] = 0.0f;

    float4 stA[2], stB[2];
    auto gload = [&](int c) {
        #pragma unroll
        for (int s = 0; s < 2; ++s) {
            stA[s] = *(const float4*)(Ab + (size_t)arA[s] * K + c * 16 + acA[s]);
            stB[s] = *(const float4*)(Wb + (size_t)(c * 16 + kB[s]) * Nn + nB);
        }
    };
    auto sstore = [&](int b) {
        __half* Ah = smh + b * GSTG;
        __half* Al = Ah + GSA;
        __half* Bh = Al + GSA;
        __half* Bl = Bh + GSB;
        #pragma unroll
        for (int s = 0; s < 2; ++s) {
            uint2 hi, lo;
            split8(stA[s], hi, lo);
            *(uint2*)&Ah[arA[s] * GASTR + acA[s]] = hi;
            *(uint2*)&Al[arA[s] * GASTR + acA[s]] = lo;
            split8(stB[s], hi, lo);
            *(uint2*)&Bh[kB[s] * GBSTR + nB] = hi;
            *(uint2*)&Bl[kB[s] * GBSTR + nB] = lo;
        }
    };

    gload(0);
    sstore(0);
    __syncthreads();

    const int lrow = lane & 15, lch = (lane >> 4) << 3;   // ldmatrix A addressing
    const int brow = ((lane >> 3) & 1) * 8 + (lane & 7);  // ldmatrix.trans B row

    for (int c = 0; c < NC; ++c) {
        if (c + 1 < NC) gload(c + 1);

        const __half* Ah = smh + (c & 1) * GSTG;
        const __half* Al = Ah + GSA;
        const __half* Bh = Al + GSA;
        const __half* Bl = Bh + GSB;

        uint32_t afh[4][4], afl[4][4], bfh[4][2], bfl[4][2];
        #pragma unroll
        for (int s = 0; s < 4; ++s) {
            const int m0 = wm * 64 + s * 16;
            const uint32_t ah = smem_u32(Ah + (m0 + lrow) * GASTR + lch);
            const uint32_t al = smem_u32(Al + (m0 + lrow) * GASTR + lch);
            LDSM_X4(afh[s][0], afh[s][1], afh[s][2], afh[s][3], ah);
            LDSM_X4(afl[s][0], afl[s][1], afl[s][2], afl[s][3], al);
        }
        #pragma unroll
        for (int np = 0; np < 2; ++np) {
            const int n0 = wn * 32 + np * 16;
            const uint32_t bh = smem_u32(Bh + brow * GBSTR + n0 + lch);
            const uint32_t bl = smem_u32(Bl + brow * GBSTR + n0 + lch);
            LDSM_X4_T(bfh[2*np][0], bfh[2*np][1], bfh[2*np+1][0], bfh[2*np+1][1], bh);
            LDSM_X4_T(bfl[2*np][0], bfl[2*np][1], bfl[2*np+1][0], bfl[2*np+1][1], bl);
        }
        #pragma unroll
        for (int i = 0; i < 4; ++i)
            #pragma unroll
            for (int j = 0; j < 4; ++j) {
                mma16816(acc[i][j], afl[i], bfh[j][0], bfh[j][1]);
                mma16816(acc[i][j], afh[i], bfl[j][0], bfl[j][1]);
                mma16816(acc[i][j], afh[i], bfh[j][0], bfh[j][1]);
            }

        if (c + 1 < NC) {
            sstore((c + 1) & 1);
            __syncthreads();
        }
    }

    // ---- epilogue ----
    #pragma unroll
    for (int i = 0; i < 4; ++i) {
        const int r1 = blockIdx.y * 128 + wm * 64 + i * 16 + g;
        #pragma unroll
        for (int j = 0; j < 4; ++j) {
            const int cgl = blockIdx.x * 128 + wn * 32 + j * 8 + tig * 2;
            if (MODE == 0) {
                const int which = cgl >> 10;
                const int head  = (cgl >> 6) & 15;
                const int dd    = cgl & 63;
                float* base = (which == 0 ? g_q : which == 1 ? g_k : g_v);
                #pragma unroll
                for (int h2 = 0; h2 < 2; ++h2) {
                    const int r = r1 + h2 * 8;
                    const int b = r >> 11, n = r & 2047;
                    float2 v = make_float2(acc[i][j][h2 * 2], acc[i][j][h2 * 2 + 1]);
                    *(float2*)(base + ((size_t)(b * HH + head) * NN + n) * DD + dd) = v;
                }
            } else {
                const float2 bv = *(const float2*)(bias + cgl);
                #pragma unroll
                for (int h2 = 0; h2 < 2; ++h2) {
                    const int r = r1 + h2 * 8;
                    float2 v = make_float2(acc[i][j][h2 * 2] + bv.x,
                                           acc[i][j][h2 * 2 + 1] + bv.y);
                    *(float2*)(Cout + (size_t)r * Nn + cgl) = v;
                }
            }
        }
    }
}

// ===========================================================================
// Per-head LayerNorm over D=64 on q and k; q additionally scaled by sqrt(D)=8.
// ===========================================================================
__global__ __launch_bounds__(128)
void qk_ln_kernel(const float* __restrict__ ln_w, const float* __restrict__ ln_b)
{
    const int R = BB * HH * NN;
    int row  = blockIdx.x * 4 + (threadIdx.x >> 5);
    int lane = threadIdx.x & 31;

    float* base  = (row < R) ? g_q : g_k;
    float  extra = (row < R) ? 8.0f : 1.0f;
    int    r     = (row < R) ? row : (row - R);

    float* p = base + (size_t)r * DD;
    float x0 = p[lane];
    float x1 = p[lane + 32];
    float s  = x0 + x1;
    float ss = x0 * x0 + x1 * x1;
    #pragma unroll
    for (int o = 16; o > 0; o >>= 1) {
        s  += __shfl_xor_sync(0xffffffffu, s,  o);
        ss += __shfl_xor_sync(0xffffffffu, ss, o);
    }
    float mu  = s * (1.0f / 64.0f);
    float var = ss * (1.0f / 64.0f) - mu * mu;
    float inv = rsqrtf(var + 1e-5f);
    p[lane]      = ((x0 - mu) * inv * ln_w[lane]      + ln_b[lane])      * extra;
    p[lane + 32] = ((x1 - mu) * inv * ln_w[lane + 32] + ln_b[lane + 32]) * extra;
}

// ===========================================================================
// Tensor-core causal flash attention (all-fp16 3-term MMAs).
// CTA: 128 q-rows of one (b,h); 8 warps x 16 rows; key tiles of 64.
// S = QK^T: fp16 m16n8k16, Q hi/lo packed in regs; K stored TRANSPOSED
//           [d][key] fp16 hi/lo -> b-frags via ldmatrix.x4.trans.
// P.V: fp16 m16n8k16 3-term; V [key][d] fp16 hi/lo via ldmatrix.x4.trans.
// ===========================================================================
#define KTSTR 72     // K^T smem stride (halves per d-row)
#define VSTR  72     // V smem stride (halves per key-row)
#define FL_SMEM (4 * 64 * 72 * 2)    // 36864 B (aliases fp32 Q staging, 34816 B)

__global__ __launch_bounds__(256, 1)
void flash_mma()
{
    extern __shared__ __align__(1024) char fsm[];
    __half* Kthi = (__half*)fsm;                 // [64 d][KTSTR]
    __half* Ktlo = Kthi + 64 * KTSTR;
    __half* Vhi  = Ktlo + 64 * KTSTR;            // [64 key][VSTR]
    __half* Vlo  = Vhi + 64 * VSTR;
    float*  Qst  = (float*)fsm;                  // staging alias (used first)

    const int bh  = blockIdx.y;
    const int qi  = blockIdx.x;
    const int tid = threadIdx.x;
    const int wid = tid >> 5, lane = tid & 31;
    const int g   = lane >> 2, tig = lane & 3;

    const float* Qg = g_q + (size_t)bh * NN * DD + (size_t)qi * 128 * DD;
    const float* Kg = g_k + (size_t)bh * NN * DD;
    const float* Vg = g_v + (size_t)bh * NN * DD;

    // ---- stage Q (fp32), then pack per-warp fp16 hi/lo a-frags ----
    #pragma unroll
    for (int s = 0; s < 8; ++s) {
        int idx = tid + s * 256;
        int r = idx >> 4, c = (idx & 15) << 2;
        *(float4*)&Qst[r * 68 + c] = *(const float4*)(Qg + r * DD + c);
    }
    __syncthreads();

    uint32_t qh[4][4], ql[4][4];
    {
        const int r0 = (wid * 16 + g) * 68;
        const int r1 = (wid * 16 + g + 8) * 68;
        #pragma unroll
        for (int kk = 0; kk < 4; ++kk) {
            const int b0 = kk * 16 + 2 * tig;
            float2 q00 = *(float2*)&Qst[r0 + b0];
            float2 q10 = *(float2*)&Qst[r1 + b0];
            float2 q01 = *(float2*)&Qst[r0 + b0 + 8];
            float2 q11 = *(float2*)&Qst[r1 + b0 + 8];
            splitp(q00.x, q00.y, qh[kk][0], ql[kk][0]);
            splitp(q10.x, q10.y, qh[kk][1], ql[kk][1]);
            splitp(q01.x, q01.y, qh[kk][2], ql[kk][2]);
            splitp(q11.x, q11.y, qh[kk][3], ql[kk][3]);
        }
    }

    float m0 = -1e30f, m1 = -1e30f, l0 = 0.0f, l1 = 0.0f;
    float o[8][4];
    #pragma unroll
    for (int j = 0; j < 8; ++j)
        #pragma unroll
        for (int r = 0; r < 4; ++r) o[j][r] = 0.0f;

    const int brow = ((lane >> 3) & 1) * 8 + (lane & 7);
    const int bch  = (lane >> 4) << 3;
    const int kend = 2 * qi + 1;

    for (int kj = 0; kj <= kend; ++kj) {
        __syncthreads();                 // prior-tile consumers done (covers Q)
        // ---- load K (transposed, fp16 hi/lo) and V (fp16 hi/lo) ----
        const float* kg = Kg + (size_t)kj * 64 * DD;
        const float* vg = Vg + (size_t)kj * 64 * DD;
        #pragma unroll
        for (int s = 0; s < 4; ++s) {
            int idx = tid + s * 256;
            int key = idx >> 4, c = (idx & 15) << 2;
            float4 kv = *(const float4*)(kg + key * DD + c);
            #pragma unroll
            for (int i = 0; i < 4; ++i) {
                float x = (&kv.x)[i];
                __half hh = __float2half_rn(x);
                __half hl = __float2half_rn(x - __half2float(hh));
                Kthi[(c + i) * KTSTR + key] = hh;
                Ktlo[(c + i) * KTSTR + key] = hl;
            }
            float4 vv = *(const float4*)(vg + key * DD + c);
            uint2 hi, lo;
            split8(vv, hi, lo);
            *(uint2*)&Vhi[key * VSTR + c] = hi;
            *(uint2*)&Vlo[key * VSTR + c] = lo;
        }
        __syncthreads();

        // ---- S = Q K^T (fp16 3-term) ----
        float sf[8][4];
        #pragma unroll
        for (int j = 0; j < 8; ++j)
            #pragma unroll
            for (int r = 0; r < 4; ++r) sf[j][r] = 0.0f;

        #pragma unroll
        for (int kk = 0; kk < 4; ++kk) {
            #pragma unroll
            for (int jp = 0; jp < 4; ++jp) {
                const int kr = kk * 16 + brow;
                const int cn = jp * 16 + bch;
                uint32_t b0, b1, b2, b3, c0, c1, c2, c3;
                LDSM_X4_T(b0, b1, b2, b3, smem_u32(Kthi + kr * KTSTR + cn));
                LDSM_X4_T(c0, c1, c2, c3, smem_u32(Ktlo + kr * KTSTR + cn));
                mma16816(sf[2*jp],   ql[kk], b0, b1);
                mma16816(sf[2*jp],   qh[kk], c0, c1);
                mma16816(sf[2*jp],   qh[kk], b0, b1);
                mma16816(sf[2*jp+1], ql[kk], b2, b3);
                mma16816(sf[2*jp+1], qh[kk], c2, c3);
                mma16816(sf[2*jp+1], qh[kk], b2, b3);
            }
        }

        // ---- causal mask on diagonal tiles ----
        if (kj >= 2 * qi) {
            const int row0 = qi * 128 + wid * 16 + g;
            const int row1 = row0 + 8;
            #pragma unroll
            for (int j = 0; j < 8; ++j) {
                const int c0 = kj * 64 + j * 8 + tig * 2;
                if (row0 < c0)     sf[j][0] = -1e30f;
                if (row0 < c0 + 1) sf[j][1] = -1e30f;
                if (row1 < c0)     sf[j][2] = -1e30f;
                if (row1 < c0 + 1) sf[j][3] = -1e30f;
            }
        }

        // ---- online softmax (rows g, g+8; quad-replicated over tig) ----
        float mx0 = -1e30f, mx1 = -1e30f;
        #pragma unroll
        for (int j = 0; j < 8; ++j) {
            mx0 = fmaxf(mx0, fmaxf(sf[j][0], sf[j][1]));
            mx1 = fmaxf(mx1, fmaxf(sf[j][2], sf[j][3]));
        }
        mx0 = fmaxf(mx0, __shfl_xor_sync(0xffffffffu, mx0, 1));
        mx0 = fmaxf(mx0, __shfl_xor_sync(0xffffffffu, mx0, 2));
        mx1 = fmaxf(mx1, __shfl_xor_sync(0xffffffffu, mx1, 1));
        mx1 = fmaxf(mx1, __shfl_xor_sync(0xffffffffu, mx1, 2));
        float mn0 = fmaxf(m0, mx0), mn1 = fmaxf(m1, mx1);
        float a0 = __expf(m0 - mn0), a1 = __expf(m1 - mn1);
        m0 = mn0; m1 = mn1;
        float rs0 = 0.0f, rs1 = 0.0f;
        #pragma unroll
        for (int j = 0; j < 8; ++j) {
            sf[j][0] = __expf(sf[j][0] - mn0); rs0 += sf[j][0];
            sf[j][1] = __expf(sf[j][1] - mn0); rs0 += sf[j][1];
            sf[j][2] = __expf(sf[j][2] - mn1); rs1 += sf[j][2];
            sf[j][3] = __expf(sf[j][3] - mn1); rs1 += sf[j][3];
        }
        rs0 += __shfl_xor_sync(0xffffffffu, rs0, 1);
        rs0 += __shfl_xor_sync(0xffffffffu, rs0, 2);
        rs1 += __shfl_xor_sync(0xffffffffu, rs1, 1);
        rs1 += __shfl_xor_sync(0xffffffffu, rs1, 2);
        l0 = l0 * a0 + rs0;
        l1 = l1 * a1 + rs1;
        #pragma unroll
        for (int j = 0; j < 8; ++j) {
            o[j][0] *= a0; o[j][1] *= a0;
            o[j][2] *= a1; o[j][3] *= a1;
        }

        // ---- P fragments (fp16 hi + lo) from S c-frags ----
        uint32_t ph[4][4], pl[4][4];
        #pragma unroll
        for (int t = 0; t < 4; ++t) {
            const int j0 = 2 * t, j1 = 2 * t + 1;
            splitp(sf[j0][0], sf[j0][1], ph[t][0], pl[t][0]);
            splitp(sf[j0][2], sf[j0][3], ph[t][1], pl[t][1]);
            splitp(sf[j1][0], sf[j1][1], ph[t][2], pl[t][2]);
            splitp(sf[j1][2], sf[j1][3], ph[t][3], pl[t][3]);
        }

        // ---- O += P V  (fp16 3-term, V frags via ldmatrix.x4.trans) ----
        #pragma unroll
        for (int t = 0; t < 4; ++t) {
            const int row = t * 16 + brow;
            #pragma unroll
            for (int jp = 0; jp < 4; ++jp) {
                const int col = jp * 16 + bch;
                uint32_t h0, h1, h2, h3, e0, e1, e2, e3;
                LDSM_X4_T(h0, h1, h2, h3, smem_u32(Vhi + row * VSTR + col));
                LDSM_X4_T(e0, e1, e2, e3, smem_u32(Vlo + row * VSTR + col));
                mma16816(o[2 * jp],     pl[t], h0, h1);
                mma16816(o[2 * jp],     ph[t], e0, e1);
                mma16816(o[2 * jp],     ph[t], h0, h1);
                mma16816(o[2 * jp + 1], pl[t], h2, h3);
                mma16816(o[2 * jp + 1], ph[t], e2, e3);
                mma16816(o[2 * jp + 1], ph[t], h2, h3);
            }
        }
    }

    // ---- finalize, scatter to [B,N,H,D] ----
    const int b = bh >> 4;
    const int h = bh & 15;
    const float inv0 = 1.0f / l0, inv1 = 1.0f / l1;
    const int n0 = qi * 128 + wid * 16 + g;
    const int n1 = n0 + 8;
    #pragma unroll
    for (int j = 0; j < 8; ++j) {
        const int d = j * 8 + tig * 2;
        *(float2*)(g_ao + (((size_t)b * NN + n0) * HH + h) * DD + d) =
            make_float2(o[j][0] * inv0, o[j][1] * inv0);
        *(float2*)(g_ao + (((size_t)b * NN + n1) * HH + h) * DD + d) =
            make_float2(o[j][2] * inv1, o[j][3] * inv1);
    }
}

// ===========================================================================
extern "C" void kernel_launch(void* const* d_in, const int* in_sizes, int n_in,
                              void* d_out, int out_size)
{
    const float* x      = (const float*)d_in[0];
    const float* w_qkv  = (const float*)d_in[1];
    const float* w_proj = (const float*)d_in[2];
    const float* b_proj = (const float*)d_in[3];
    const float* ln_w   = (const float*)d_in[4];
    const float* ln_b   = (const float*)d_in[5];
    float* out = (float*)d_out;

    cudaFuncSetAttribute(tc_gemm<0>, cudaFuncAttributeMaxDynamicSharedMemorySize, GEMM_SMEM);
    cudaFuncSetAttribute(tc_gemm<1>, cudaFuncAttributeMaxDynamicSharedMemorySize, GEMM_SMEM);
    cudaFuncSetAttribute(flash_mma, cudaFuncAttributeMaxDynamicSharedMemorySize, FL_SMEM);

    // 1) QKV projection (fp16 3-term mma.sync) + scatter to [B,H,N,D]
    tc_gemm<0><<<dim3(24, 32), 256, GEMM_SMEM>>>(x, w_qkv, nullptr, nullptr);

    // 2) per-head LayerNorm on q,k (+ sqrt(D) folded into q)
    qk_ln_kernel<<<(2 * BB * HH * NN) / 4, 128>>>(ln_w, ln_b);

    // 3) tensor-core causal flash attention
    flash_mma<<<dim3(NN / 128, BB * HH), 256, FL_SMEM>>>();

    // 4) output projection + bias (fp16 3-term mma.sync)
    tc_gemm<1><<<dim3(8, 32), 256, GEMM_SMEM>>>(nullptr, w_proj, b_proj, out);
}

// round 8
// speedup vs baseline: 2.8752x; 1.0734x over previous
#include <cuda_runtime.h>
#include <cuda_fp16.h>
#include <math.h>
#include <stdint.h>

#define BB 2
#define NN 2048
#define CC 1024
#define HH 16
#define DD 64

// ---- scratch (device globals; allocation-free per harness rules) ----
__device__ float  g_q [BB*HH*NN*DD];          // fp32 q (pre-LN)
__device__ float  g_k [BB*HH*NN*DD];          // fp32 k (pre-LN)
__device__ __half g_qh[BB*HH*NN*DD], g_ql[BB*HH*NN*DD];   // post-LN fp16 hi/lo
__device__ __half g_kh[BB*HH*NN*DD], g_kl[BB*HH*NN*DD];
__device__ __half g_vh[BB*HH*NN*DD], g_vl[BB*HH*NN*DD];
__device__ __half g_aoh[BB*NN*CC],  g_aol[BB*NN*CC];      // attn out hi/lo
__device__ __half g_xh[BB*NN*CC],   g_xl[BB*NN*CC];       // x hi/lo
__device__ __half g_wqh[CC*3*CC],   g_wql[CC*3*CC];       // w_qkv hi/lo
__device__ __half g_wph[CC*CC],     g_wpl[CC*CC];         // w_proj hi/lo

// ===========================================================================
// helpers
// ===========================================================================
__device__ __forceinline__ void mma16816(float* d, const uint32_t* a,
                                         uint32_t b0, uint32_t b1) {
    asm volatile(
        "mma.sync.aligned.m16n8k16.row.col.f32.f16.f16.f32 "
        "{%0,%1,%2,%3}, {%4,%5,%6,%7}, {%8,%9}, {%0,%1,%2,%3};"
        : "+f"(d[0]), "+f"(d[1]), "+f"(d[2]), "+f"(d[3])
        : "r"(a[0]), "r"(a[1]), "r"(a[2]), "r"(a[3]), "r"(b0), "r"(b1));
}
__device__ __forceinline__ uint32_t smem_u32(const void* p) {
    uint32_t a;
    asm("{ .reg .u64 t; cvta.to.shared.u64 t, %1; cvt.u32.u64 %0, t; }"
        : "=r"(a) : "l"(p));
    return a;
}
#define LDSM_X4(r0, r1, r2, r3, addr) \
    asm volatile("ldmatrix.sync.aligned.m8n8.x4.shared.b16 " \
                 "{%0,%1,%2,%3}, [%4];" \
                 : "=r"(r0), "=r"(r1), "=r"(r2), "=r"(r3) : "r"(addr))
#define LDSM_X4_T(r0, r1, r2, r3, addr) \
    asm volatile("ldmatrix.sync.aligned.m8n8.x4.trans.shared.b16 " \
                 "{%0,%1,%2,%3}, [%4];" \
                 : "=r"(r0), "=r"(r1), "=r"(r2), "=r"(r3) : "r"(addr))
#define CPA16(dst, src) \
    asm volatile("cp.async.cg.shared.global [%0], [%1], 16;" :: "r"(dst), "l"(src))
#define CPA_COMMIT() asm volatile("cp.async.commit_group;" ::)
#define CPA_WAIT(n)  asm volatile("cp.async.wait_group %0;" :: "n"(n))

// split (a,b) into fp16 hi pair + fp16 residual pair
__device__ __forceinline__ void splitp(float a, float b, uint32_t& hi, uint32_t& lo) {
    __half2 h = __floats2half2_rn(a, b);
    float2 f = __half22float2(h);
    __half2 l = __floats2half2_rn(a - f.x, b - f.y);
    hi = *(uint32_t*)&h;
    lo = *(uint32_t*)&l;
}
__device__ __forceinline__ void split8(float4 v, uint2& hi, uint2& lo) {
    splitp(v.x, v.y, hi.x, lo.x);
    splitp(v.z, v.w, hi.y, lo.y);
}

// ===========================================================================
// fp32 -> fp16 hi/lo streaming conversion
// ===========================================================================
__global__ __launch_bounds__(256)
void f2h_split(const float* __restrict__ src, __half* __restrict__ hi,
               __half* __restrict__ lo, int n4)
{
    int i = blockIdx.x * blockDim.x + threadIdx.x;
    if (i >= n4) return;
    float4 v = ((const float4*)src)[i];
    uint2 h, l;
    split8(v, h, l);
    ((uint2*)hi)[i] = h;
    ((uint2*)lo)[i] = l;
}

// ===========================================================================
// fp16 3-term GEMM, cp.async 4-stage pipeline.
// C[4096 x Nn] = A[4096 x 1024] @ W[1024 x Nn]; CTA 128x128, BK=16.
// 8 warps 2(m) x 4(n).  All operands pre-split fp16 hi/lo in gmem.
// MODE 0: A=x, W=w_qkv (Nn=3072) -> q/k fp32 (for LN) + v fp16 hi/lo
// MODE 1: A=ao hi/lo, W=w_proj (Nn=1024), +bias -> Cout fp32
// ===========================================================================
#define STGH 10496            // halves per stage: A 2*128*24 + B 2*16*136
#define STGB (STGH * 2)
#define OAL  3072             // half offsets within stage
#define OBH  6144
#define OBL  8320
#define GEMM_SMEM (4 * STGB)  // 83968 B

template<int MODE>
__global__ __launch_bounds__(256, 2)
void tc_gemm(const float* __restrict__ bias, float* __restrict__ Cout)
{
    constexpr int K  = 1024;
    constexpr int NC = K / 16;
    constexpr int Nn = (MODE == 0) ? 3072 : 1024;

    const __half* Agh = (MODE == 0) ? g_xh  : g_aoh;
    const __half* Agl = (MODE == 0) ? g_xl  : g_aol;
    const __half* Bgh = (MODE == 0) ? g_wqh : g_wph;
    const __half* Bgl = (MODE == 0) ? g_wql : g_wpl;

    extern __shared__ __half smh[];
    const uint32_t smb = smem_u32(smh);

    const int tid  = threadIdx.x;
    const int wid  = tid >> 5, lane = tid & 31;
    const int wm   = wid & 1,  wn   = wid >> 1;
    const int g    = lane >> 2, tig = lane & 3;
    const int rowg0 = blockIdx.y * 128;
    const int nblk  = blockIdx.x * 128;

    auto issue = [&](int c, int st) {
        const uint32_t sb = smb + st * STGB;
        #pragma unroll
        for (int s = 0; s < 2; ++s) {             // A: 512 16B chunks
            int idx = tid + s * 256;
            int row = idx >> 2, rem = idx & 3;
            int arr = rem >> 1, ch = rem & 1;
            const __half* gp = (arr ? Agl : Agh)
                + (size_t)(rowg0 + row) * K + c * 16 + ch * 8;
            CPA16(sb + (arr ? OAL * 2 : 0) + (row * 24 + ch * 8) * 2, gp);
        }
        #pragma unroll
        for (int s = 0; s < 2; ++s) {             // B: 512 16B chunks
            int idx = tid + s * 256;
            int arr = idx >> 8, rr = (idx >> 4) & 15, ch = idx & 15;
            const __half* gp = (arr ? Bgl : Bgh)
                + (size_t)(c * 16 + rr) * Nn + nblk + ch * 8;
            CPA16(sb + (arr ? OBL * 2 : OBH * 2) + (rr * 136 + ch * 8) * 2, gp);
        }
    };

    float acc[4][4][4];
    #pragma unroll
    for (int i = 0; i < 4; ++i)
        #pragma unroll
        for (int j = 0; j < 4; ++j)
            #pragma unroll
            for (int r = 0; r < 4; ++r) acc[i][j][r] = 0.0f;

    issue(0, 0); CPA_COMMIT();
    issue(1, 1); CPA_COMMIT();
    issue(2, 2); CPA_COMMIT();

    const int lrow = lane & 15, lch = (lane >> 4) << 3;
    const int brow = ((lane >> 3) & 1) * 8 + (lane & 7);

    for (int c = 0; c < NC; ++c) {
        CPA_WAIT(2);
        __syncthreads();
        const int st = c & 3;
        const __half* Ah = smh + st * STGH;
        const __half* Al = Ah + OAL;
        const __half* Bh = smh + st * STGH + OBH;
        const __half* Bl = smh + st * STGH + OBL;

        uint32_t afh[4][4], afl[4][4], bfh[4][2], bfl[4][2];
        #pragma unroll
        for (int s = 0; s < 4; ++s) {
            const int m0 = wm * 64 + s * 16;
            LDSM_X4(afh[s][0], afh[s][1], afh[s][2], afh[s][3],
                    smem_u32(Ah + (m0 + lrow) * 24 + lch));
            LDSM_X4(afl[s][0], afl[s][1], afl[s][2], afl[s][3],
                    smem_u32(Al + (m0 + lrow) * 24 + lch));
        }
        #pragma unroll
        for (int np = 0; np < 2; ++np) {
            const int n0 = wn * 32 + np * 16;
            LDSM_X4_T(bfh[2*np][0], bfh[2*np][1], bfh[2*np+1][0], bfh[2*np+1][1],
                      smem_u32(Bh + brow * 136 + n0 + lch));
            LDSM_X4_T(bfl[2*np][0], bfl[2*np][1], bfl[2*np+1][0], bfl[2*np+1][1],
                      smem_u32(Bl + brow * 136 + n0 + lch));
        }
        #pragma unroll
        for (int i = 0; i < 4; ++i)
            #pragma unroll
            for (int j = 0; j < 4; ++j) {
                mma16816(acc[i][j], afl[i], bfh[j][0], bfh[j][1]);
                mma16816(acc[i][j], afh[i], bfl[j][0], bfl[j][1]);
                mma16816(acc[i][j], afh[i], bfh[j][0], bfh[j][1]);
            }
        __syncthreads();
        if (c + 3 < NC) issue(c + 3, (c + 3) & 3);
        CPA_COMMIT();
    }

    // ---- epilogue ----
    #pragma unroll
    for (int i = 0; i < 4; ++i) {
        const int r1 = rowg0 + wm * 64 + i * 16 + g;
        #pragma unroll
        for (int j = 0; j < 4; ++j) {
            const int cgl = nblk + wn * 32 + j * 8 + tig * 2;
            if (MODE == 0) {
                const int which = cgl >> 10;
                const int head  = (cgl >> 6) & 15;
                const int dd    = cgl & 63;
                #pragma unroll
                for (int h2 = 0; h2 < 2; ++h2) {
                    const int r = r1 + h2 * 8;
                    const int b = r >> 11, n = r & 2047;
                    const size_t off = ((size_t)(b * HH + head) * NN + n) * DD + dd;
                    float a0 = acc[i][j][h2 * 2], a1 = acc[i][j][h2 * 2 + 1];
                    if (which == 0)      *(float2*)(g_q + off) = make_float2(a0, a1);
                    else if (which == 1) *(float2*)(g_k + off) = make_float2(a0, a1);
                    else {
                        uint32_t hi, lo;
                        splitp(a0, a1, hi, lo);
                        *(uint32_t*)(g_vh + off) = hi;
                        *(uint32_t*)(g_vl + off) = lo;
                    }
                }
            } else {
                const float2 bv = *(const float2*)(bias + cgl);
                #pragma unroll
                for (int h2 = 0; h2 < 2; ++h2) {
                    const int r = r1 + h2 * 8;
                    *(float2*)(Cout + (size_t)r * Nn + cgl) =
                        make_float2(acc[i][j][h2 * 2] + bv.x,
                                    acc[i][j][h2 * 2 + 1] + bv.y);
                }
            }
        }
    }
}

// ===========================================================================
// Per-head LayerNorm (D=64) on q,k; q scaled by sqrt(D)=8; fp16 hi/lo output.
// ===========================================================================
__global__ __launch_bounds__(128)
void qk_ln_kernel(const float* __restrict__ ln_w, const float* __restrict__ ln_b)
{
    const int R = BB * HH * NN;
    int row  = blockIdx.x * 4 + (threadIdx.x >> 5);
    int lane = threadIdx.x & 31;

    const bool isq = (row < R);
    const float* src = isq ? g_q : g_k;
    __half* dh = isq ? g_qh : g_kh;
    __half* dl = isq ? g_ql : g_kl;
    float extra = isq ? 8.0f : 1.0f;
    int r = isq ? row : (row - R);

    const float* p = src + (size_t)r * DD;
    float x0 = p[lane];
    float x1 = p[lane + 32];
    float s  = x0 + x1;
    float ss = x0 * x0 + x1 * x1;
    #pragma unroll
    for (int o = 16; o > 0; o >>= 1) {
        s  += __shfl_xor_sync(0xffffffffu, s,  o);
        ss += __shfl_xor_sync(0xffffffffu, ss, o);
    }
    float mu  = s * (1.0f / 64.0f);
    float var = ss * (1.0f / 64.0f) - mu * mu;
    float inv = rsqrtf(var + 1e-5f);
    float y0 = ((x0 - mu) * inv * ln_w[lane]      + ln_b[lane])      * extra;
    float y1 = ((x1 - mu) * inv * ln_w[lane + 32] + ln_b[lane + 32]) * extra;

    __half h0 = __float2half_rn(y0);
    __half h1 = __float2half_rn(y1);
    size_t off = (size_t)r * DD + lane;
    dh[off]      = h0;
    dh[off + 32] = h1;
    dl[off]      = __float2half_rn(y0 - __half2float(h0));
    dl[off + 32] = __float2half_rn(y1 - __half2float(h1));
}

// ===========================================================================
// Tensor-core causal flash attention, pre-split fp16 inputs, cp.async
// double-buffered K/V tiles. CTA: 128 q-rows; 8 warps x 16 rows; key tile 64.
// S = QK^T: K natural [key][d] -> b-frags via NON-trans ldmatrix (row.col
//           B is col-major: transpose is free).  P.V: V [key][d] via trans.
// Reversed qi order: heaviest causal CTAs first (LPT scheduling).
// ===========================================================================
#define FSTR 72                         // smem row stride (halves)
#define ARRB (64 * FSTR * 2)            // 9216 B per array
#define BUFB (4 * ARRB)                 // 36864 B per KV buffer
#define FL_SMEM (2 * BUFB)              // 73728 B

__global__ __launch_bounds__(256)
void flash_mma()
{
    extern __shared__ __align__(1024) char fsm[];
    const uint32_t fsmb = smem_u32(fsm);

    const int bh  = blockIdx.y;
    const int qi  = (gridDim.x - 1) - blockIdx.x;   // heavy tiles first
    const int tid = threadIdx.x;
    const int wid = tid >> 5, lane = tid & 31;
    const int g   = lane >> 2, tig = lane & 3;

    const size_t hb = (size_t)bh * NN * DD;
    const size_t qb = hb + (size_t)qi * 128 * DD;

    // ---- stage Q hi/lo into smem, extract per-warp a-frags ----
    {
        __half* Qh = (__half*)fsm;
        __half* Ql = (__half*)(fsm + 18432);
        #pragma unroll
        for (int s = 0; s < 4; ++s) {
            int idx = tid + s * 256;
            int row = idx >> 3, ch = idx & 7;
            *(uint4*)&Qh[row * FSTR + ch * 8] = *(const uint4*)(g_qh + qb + row * 64 + ch * 8);
            *(uint4*)&Ql[row * FSTR + ch * 8] = *(const uint4*)(g_ql + qb + row * 64 + ch * 8);
        }
    }
    __syncthreads();

    uint32_t qh[4][4], ql[4][4];
    {
        const int lrow = lane & 15, lch = (lane >> 4) << 3;
        #pragma unroll
        for (int kk = 0; kk < 4; ++kk) {
            uint32_t a = fsmb + ((wid * 16 + lrow) * FSTR + kk * 16 + lch) * 2;
            LDSM_X4(qh[kk][0], qh[kk][1], qh[kk][2], qh[kk][3], a);
            LDSM_X4(ql[kk][0], ql[kk][1], ql[kk][2], ql[kk][3], a + 18432);
        }
    }
    __syncthreads();

    auto issueKV = [&](int kj, int b) {
        const size_t kb = hb + (size_t)kj * 64 * DD;
        const uint32_t sb = fsmb + b * BUFB;
        const __half* gs[4] = { g_kh + kb, g_kl + kb, g_vh + kb, g_vl + kb };
        #pragma unroll
        for (int a = 0; a < 4; ++a) {
            const uint32_t so = sb + a * ARRB;
            #pragma unroll
            for (int s = 0; s < 2; ++s) {
                int idx = tid + s * 256;
                int row = idx >> 3, ch = idx & 7;
                CPA16(so + (row * FSTR + ch * 8) * 2, gs[a] + row * 64 + ch * 8);
            }
        }
    };

    float m0 = -1e30f, m1 = -1e30f, l0 = 0.0f, l1 = 0.0f;
    float o[8][4];
    #pragma unroll
    for (int j = 0; j < 8; ++j)
        #pragma unroll
        for (int r = 0; r < 4; ++r) o[j][r] = 0.0f;

    const int lrow = lane & 15, lch = (lane >> 4) << 3;
    const int brow = ((lane >> 3) & 1) * 8 + (lane & 7);
    const int kend = 2 * qi + 1;

    issueKV(0, 0); CPA_COMMIT();

    for (int kj = 0; kj <= kend; ++kj) {
        if (kj < kend) issueKV(kj + 1, (kj + 1) & 1);
        CPA_COMMIT();
        CPA_WAIT(1);
        __syncthreads();

        const uint32_t bK  = fsmb + (kj & 1) * BUFB;           // K hi
        const uint32_t bKl = bK + ARRB;                        // K lo
        const uint32_t bV  = bK + 2 * ARRB;                    // V hi
        const uint32_t bVl = bK + 3 * ARRB;                    // V lo

        // ---- S = Q K^T (fp16 3-term, non-trans b-frags) ----
        float sf[8][4];
        #pragma unroll
        for (int j = 0; j < 8; ++j)
            #pragma unroll
            for (int r = 0; r < 4; ++r) sf[j][r] = 0.0f;

        #pragma unroll
        for (int kk = 0; kk < 4; ++kk) {
            #pragma unroll
            for (int jp = 0; jp < 4; ++jp) {
                const uint32_t off = ((jp * 16 + lrow) * FSTR + kk * 16 + lch) * 2;
                uint32_t h0, h1, h2, h3, e0, e1, e2, e3;
                LDSM_X4(h0, h1, h2, h3, bK + off);
                LDSM_X4(e0, e1, e2, e3, bKl + off);
                mma16816(sf[2*jp],   ql[kk], h0, h2);
                mma16816(sf[2*jp],   qh[kk], e0, e2);
                mma16816(sf[2*jp],   qh[kk], h0, h2);
                mma16816(sf[2*jp+1], ql[kk], h1, h3);
                mma16816(sf[2*jp+1], qh[kk], e1, e3);
                mma16816(sf[2*jp+1], qh[kk], h1, h3);
            }
        }

        // ---- causal mask on diagonal tiles ----
        if (kj >= 2 * qi) {
            const int row0 = qi * 128 + wid * 16 + g;
            const int row1 = row0 + 8;
            #pragma unroll
            for (int j = 0; j < 8; ++j) {
                const int c0 = kj * 64 + j * 8 + tig * 2;
                if (row0 < c0)     sf[j][0] = -1e30f;
                if (row0 < c0 + 1) sf[j][1] = -1e30f;
                if (row1 < c0)     sf[j][2] = -1e30f;
                if (row1 < c0 + 1) sf[j][3] = -1e30f;
            }
        }

        // ---- online softmax (rows g, g+8; quad-replicated over tig) ----
        float mx0 = -1e30f, mx1 = -1e30f;
        #pragma unroll
        for (int j = 0; j < 8; ++j) {
            mx0 = fmaxf(mx0, fmaxf(sf[j][0], sf[j][1]));
            mx1 = fmaxf(mx1, fmaxf(sf[j][2], sf[j][3]));
        }
        mx0 = fmaxf(mx0, __shfl_xor_sync(0xffffffffu, mx0, 1));
        mx0 = fmaxf(mx0, __shfl_xor_sync(0xffffffffu, mx0, 2));
        mx1 = fmaxf(mx1, __shfl_xor_sync(0xffffffffu, mx1, 1));
        mx1 = fmaxf(mx1, __shfl_xor_sync(0xffffffffu, mx1, 2));
        float mn0 = fmaxf(m0, mx0), mn1 = fmaxf(m1, mx1);
        float a0 = __expf(m0 - mn0), a1 = __expf(m1 - mn1);
        m0 = mn0; m1 = mn1;
        float rs0 = 0.0f, rs1 = 0.0f;
        #pragma unroll
        for (int j = 0; j < 8; ++j) {
            sf[j][0] = __expf(sf[j][0] - mn0); rs0 += sf[j][0];
            sf[j][1] = __expf(sf[j][1] - mn0); rs0 += sf[j][1];
            sf[j][2] = __expf(sf[j][2] - mn1); rs1 += sf[j][2];
            sf[j][3] = __expf(sf[j][3] - mn1); rs1 += sf[j][3];
        }
        rs0 += __shfl_xor_sync(0xffffffffu, rs0, 1);
        rs0 += __shfl_xor_sync(0xffffffffu, rs0, 2);
        rs1 += __shfl_xor_sync(0xffffffffu, rs1, 1);
        rs1 += __shfl_xor_sync(0xffffffffu, rs1, 2);
        l0 = l0 * a0 + rs0;
        l1 = l1 * a1 + rs1;
        #pragma unroll
        for (int j = 0; j < 8; ++j) {
            o[j][0] *= a0; o[j][1] *= a0;
            o[j][2] *= a1; o[j][3] *= a1;
        }

        // ---- P fragments (fp16 hi + lo) from S c-frags ----
        uint32_t ph[4][4], pl[4][4];
        #pragma unroll
        for (int t = 0; t < 4; ++t) {
            const int j0 = 2 * t, j1 = 2 * t + 1;
            splitp(sf[j0][0], sf[j0][1], ph[t][0], pl[t][0]);
            splitp(sf[j0][2], sf[j0][3], ph[t][1], pl[t][1]);
            splitp(sf[j1][0], sf[j1][1], ph[t][2], pl[t][2]);
            splitp(sf[j1][2], sf[j1][3], ph[t][3], pl[t][3]);
        }

        // ---- O += P V  (fp16 3-term, V frags via ldmatrix.x4.trans) ----
        #pragma unroll
        for (int t = 0; t < 4; ++t) {
            const int row = t * 16 + brow;
            #pragma unroll
            for (int jp = 0; jp < 4; ++jp) {
                const uint32_t off = (row * FSTR + jp * 16 + lch) * 2;
                uint32_t h0, h1, h2, h3, e0, e1, e2, e3;
                LDSM_X4_T(h0, h1, h2, h3, bV + off);
                LDSM_X4_T(e0, e1, e2, e3, bVl + off);
                mma16816(o[2 * jp],     pl[t], h0, h1);
                mma16816(o[2 * jp],     ph[t], e0, e1);
                mma16816(o[2 * jp],     ph[t], h0, h1);
                mma16816(o[2 * jp + 1], pl[t], h2, h3);
                mma16816(o[2 * jp + 1], ph[t], e2, e3);
                mma16816(o[2 * jp + 1], ph[t], h2, h3);
            }
        }
        __syncthreads();
    }

    // ---- finalize, write ao as fp16 hi/lo [B,N,(H D)] ----
    const int b = bh >> 4;
    const int h = bh & 15;
    const float inv0 = 1.0f / l0, inv1 = 1.0f / l1;
    const int n0 = qi * 128 + wid * 16 + g;
    const int n1 = n0 + 8;
    #pragma unroll
    for (int j = 0; j < 8; ++j) {
        const int d = j * 8 + tig * 2;
        const size_t o0 = (((size_t)b * NN + n0) * HH + h) * DD + d;
        const size_t o1 = (((size_t)b * NN + n1) * HH + h) * DD + d;
        uint32_t hi, lo;
        splitp(o[j][0] * inv0, o[j][1] * inv0, hi, lo);
        *(uint32_t*)(g_aoh + o0) = hi;
        *(uint32_t*)(g_aol + o0) = lo;
        splitp(o[j][2] * inv1, o[j][3] * inv1, hi, lo);
        *(uint32_t*)(g_aoh + o1) = hi;
        *(uint32_t*)(g_aol + o1) = lo;
    }
}

// ===========================================================================
extern "C" void kernel_launch(void* const* d_in, const int* in_sizes, int n_in,
                              void* d_out, int out_size)
{
    const float* x      = (const float*)d_in[0];
    const float* w_qkv  = (const float*)d_in[1];
    const float* w_proj = (const float*)d_in[2];
    const float* b_proj = (const float*)d_in[3];
    const float* ln_w   = (const float*)d_in[4];
    const float* ln_b   = (const float*)d_in[5];
    float* out = (float*)d_out;

    cudaFuncSetAttribute(tc_gemm<0>, cudaFuncAttributeMaxDynamicSharedMemorySize, GEMM_SMEM);
    cudaFuncSetAttribute(tc_gemm<1>, cudaFuncAttributeMaxDynamicSharedMemorySize, GEMM_SMEM);
    cudaFuncSetAttribute(flash_mma, cudaFuncAttributeMaxDynamicSharedMemorySize, FL_SMEM);

    __half *xh, *xl, *wqh, *wql, *wph, *wpl;
    cudaGetSymbolAddress((void**)&xh,  g_xh);  cudaGetSymbolAddress((void**)&xl,  g_xl);
    cudaGetSymbolAddress((void**)&wqh, g_wqh); cudaGetSymbolAddress((void**)&wql, g_wql);
    cudaGetSymbolAddress((void**)&wph, g_wph); cudaGetSymbolAddress((void**)&wpl, g_wpl);

    // 0) pre-split operands to fp16 hi/lo
    f2h_split<<<4096, 256>>>(x,      xh,  xl,  BB*NN*CC/4);
    f2h_split<<<3072, 256>>>(w_qkv,  wqh, wql, CC*3*CC/4);
    f2h_split<<<1024, 256>>>(w_proj, wph, wpl, CC*CC/4);

    // 1) QKV projection (cp.async pipelined) -> q/k fp32, v fp16 hi/lo
    tc_gemm<0><<<dim3(24, 32), 256, GEMM_SMEM>>>(nullptr, nullptr);

    // 2) per-head LayerNorm on q,k -> fp16 hi/lo
    qk_ln_kernel<<<(2 * BB * HH * NN) / 4, 128>>>(ln_w, ln_b);

    // 3) causal flash attention -> ao fp16 hi/lo
    flash_mma<<<dim3(NN / 128, BB * HH), 256, FL_SMEM>>>();

    // 4) output projection + bias
    tc_gemm<1><<<dim3(8, 32), 256, GEMM_SMEM>>>(b_proj, out);
}

// round 9
// speedup vs baseline: 3.1428x; 1.0931x over previous
#include <cuda_runtime.h>
#include <cuda_fp16.h>
#include <math.h>
#include <stdint.h>

#define BB 2
#define NN 2048
#define CC 1024
#define HH 16
#define DD 64

// ---- scratch (device globals; allocation-free per harness rules) ----
__device__ float  g_q [BB*HH*NN*DD];          // fp32 q (pre-LN)
__device__ float  g_k [BB*HH*NN*DD];          // fp32 k (pre-LN)
__device__ __half g_qh[BB*HH*NN*DD], g_ql[BB*HH*NN*DD];   // post-LN fp16 hi/lo
__device__ __half g_kh[BB*HH*NN*DD], g_kl[BB*HH*NN*DD];
__device__ __half g_vh[BB*HH*NN*DD], g_vl[BB*HH*NN*DD];
__device__ __half g_aoh[BB*NN*CC],  g_aol[BB*NN*CC];      // attn out hi/lo
__device__ __half g_xh[BB*NN*CC],   g_xl[BB*NN*CC];       // x hi/lo
__device__ __half g_wqh[CC*3*CC],   g_wql[CC*3*CC];       // w_qkv hi/lo
__device__ __half g_wph[CC*CC],     g_wpl[CC*CC];         // w_proj hi/lo

// ===========================================================================
// helpers
// ===========================================================================
__device__ __forceinline__ void mma16816(float* d, const uint32_t* a,
                                         uint32_t b0, uint32_t b1) {
    asm volatile(
        "mma.sync.aligned.m16n8k16.row.col.f32.f16.f16.f32 "
        "{%0,%1,%2,%3}, {%4,%5,%6,%7}, {%8,%9}, {%0,%1,%2,%3};"
        : "+f"(d[0]), "+f"(d[1]), "+f"(d[2]), "+f"(d[3])
        : "r"(a[0]), "r"(a[1]), "r"(a[2]), "r"(a[3]), "r"(b0), "r"(b1));
}
__device__ __forceinline__ uint32_t smem_u32(const void* p) {
    uint32_t a;
    asm("{ .reg .u64 t; cvta.to.shared.u64 t, %1; cvt.u32.u64 %0, t; }"
        : "=r"(a) : "l"(p));
    return a;
}
#define LDSM_X4(r0, r1, r2, r3, addr) \
    asm volatile("ldmatrix.sync.aligned.m8n8.x4.shared.b16 " \
                 "{%0,%1,%2,%3}, [%4];" \
                 : "=r"(r0), "=r"(r1), "=r"(r2), "=r"(r3) : "r"(addr))
#define LDSM_X4_T(r0, r1, r2, r3, addr) \
    asm volatile("ldmatrix.sync.aligned.m8n8.x4.trans.shared.b16 " \
                 "{%0,%1,%2,%3}, [%4];" \
                 : "=r"(r0), "=r"(r1), "=r"(r2), "=r"(r3) : "r"(addr))
#define CPA16(dst, src) \
    asm volatile("cp.async.cg.shared.global [%0], [%1], 16;" :: "r"(dst), "l"(src))
#define CPA_COMMIT() asm volatile("cp.async.commit_group;" ::)
#define CPA_WAIT(n)  asm volatile("cp.async.wait_group %0;" :: "n"(n))

// split (a,b) into fp16 hi pair + fp16 residual pair
__device__ __forceinline__ void splitp(float a, float b, uint32_t& hi, uint32_t& lo) {
    __half2 h = __floats2half2_rn(a, b);
    float2 f = __half22float2(h);
    __half2 l = __floats2half2_rn(a - f.x, b - f.y);
    hi = *(uint32_t*)&h;
    lo = *(uint32_t*)&l;
}
__device__ __forceinline__ void split8(float4 v, uint2& hi, uint2& lo) {
    splitp(v.x, v.y, hi.x, lo.x);
    splitp(v.z, v.w, hi.y, lo.y);
}

// ===========================================================================
// fp32 -> fp16 hi/lo streaming conversion
// ===========================================================================
__global__ __launch_bounds__(256)
void f2h_split(const float* __restrict__ src, __half* __restrict__ hi,
               __half* __restrict__ lo, int n4)
{
    int i = blockIdx.x * blockDim.x + threadIdx.x;
    if (i >= n4) return;
    float4 v = ((const float4*)src)[i];
    uint2 h, l;
    split8(v, h, l);
    ((uint2*)hi)[i] = h;
    ((uint2*)lo)[i] = l;
}

// ===========================================================================
// fp16 3-term GEMM, cp.async double-buffered, BK=32, ONE sync per chunk.
// C[4096 x Nn] = A[4096 x 1024] @ W[1024 x Nn]; CTA 128x128.
// 8 warps 2(m) x 4(n); 96 MMAs between barriers.
// MODE 0: A=x, W=w_qkv (Nn=3072) -> q/k fp32 + v fp16 hi/lo
// MODE 1: A=ao hi/lo, W=w_proj (Nn=1024), +bias -> Cout fp32
// ===========================================================================
#define ASTR 40                        // A smem stride (halves), conflict-free
#define BSTR 136                       // B smem stride (halves), conflict-free
#define OAL  (128 * ASTR)              // 5120 half offset of A-lo
#define OBH  (2 * 128 * ASTR)          // 10240
#define OBL  (OBH + 32 * BSTR)         // 14592
#define STGH (OBH + 2 * 32 * BSTR)     // 18944 halves / stage
#define STGB (STGH * 2)                // 37888 B
#define GEMM_SMEM (2 * STGB)           // 75776 B

template<int MODE>
__global__ __launch_bounds__(256, 2)
void tc_gemm(const float* __restrict__ bias, float* __restrict__ Cout)
{
    constexpr int K  = 1024;
    constexpr int NC = K / 32;                    // 32 chunks
    constexpr int Nn = (MODE == 0) ? 3072 : 1024;

    const __half* Agh = (MODE == 0) ? g_xh  : g_aoh;
    const __half* Agl = (MODE == 0) ? g_xl  : g_aol;
    const __half* Bgh = (MODE == 0) ? g_wqh : g_wph;
    const __half* Bgl = (MODE == 0) ? g_wql : g_wpl;

    extern __shared__ __half smh[];
    const uint32_t smb = smem_u32(smh);

    const int tid  = threadIdx.x;
    const int wid  = tid >> 5, lane = tid & 31;
    const int wm   = wid & 1,  wn   = wid >> 1;
    const int g    = lane >> 2, tig = lane & 3;
    const int rowg0 = blockIdx.y * 128;
    const int nblk  = blockIdx.x * 128;

    auto issue = [&](int c, int st) {
        const uint32_t sb = smb + st * STGB;
        #pragma unroll
        for (int s = 0; s < 4; ++s) {             // A: 1024 16B chunks
            int idx = tid + s * 256;
            int arr = idx >> 9, rem = idx & 511;
            int row = rem >> 2, ch = rem & 3;
            const __half* gp = (arr ? Agl : Agh)
                + (size_t)(rowg0 + row) * K + c * 32 + ch * 8;
            CPA16(sb + ((arr ? OAL : 0) + row * ASTR + ch * 8) * 2, gp);
        }
        #pragma unroll
        for (int s = 0; s < 4; ++s) {             // B: 1024 16B chunks
            int idx = tid + s * 256;
            int arr = idx >> 9, rem = idx & 511;
            int rr = rem >> 4, ch = rem & 15;
            const __half* gp = (arr ? Bgl : Bgh)
                + (size_t)(c * 32 + rr) * Nn + nblk + ch * 8;
            CPA16(sb + ((arr ? OBL : OBH) + rr * BSTR + ch * 8) * 2, gp);
        }
    };

    float acc[4][4][4];
    #pragma unroll
    for (int i = 0; i < 4; ++i)
        #pragma unroll
        for (int j = 0; j < 4; ++j)
            #pragma unroll
            for (int r = 0; r < 4; ++r) acc[i][j][r] = 0.0f;

    issue(0, 0);
    CPA_COMMIT();

    const int lrow = lane & 15, lch = (lane >> 4) << 3;
    const int brow = ((lane >> 3) & 1) * 8 + (lane & 7);

    for (int c = 0; c < NC; ++c) {
        CPA_WAIT(0);
        __syncthreads();                 // chunk c ready; slot (c+1)&1 free
        if (c + 1 < NC) {
            issue(c + 1, (c + 1) & 1);
            CPA_COMMIT();
        }

        const int st = c & 1;
        const __half* Ah = smh + st * STGH;
        const __half* Al = Ah + OAL;
        const __half* Bh = smh + st * STGH + OBH;
        const __half* Bl = smh + st * STGH + OBL;

        #pragma unroll
        for (int ks = 0; ks < 2; ++ks) {
            uint32_t afh[4][4], afl[4][4], bfh[4][2], bfl[4][2];
            #pragma unroll
            for (int s = 0; s < 4; ++s) {
                const int m0 = wm * 64 + s * 16;
                LDSM_X4(afh[s][0], afh[s][1], afh[s][2], afh[s][3],
                        smem_u32(Ah + (m0 + lrow) * ASTR + ks * 16 + lch));
                LDSM_X4(afl[s][0], afl[s][1], afl[s][2], afl[s][3],
                        smem_u32(Al + (m0 + lrow) * ASTR + ks * 16 + lch));
            }
            #pragma unroll
            for (int np = 0; np < 2; ++np) {
                const int n0 = wn * 32 + np * 16;
                LDSM_X4_T(bfh[2*np][0], bfh[2*np][1], bfh[2*np+1][0], bfh[2*np+1][1],
                          smem_u32(Bh + (ks * 16 + brow) * BSTR + n0 + lch));
                LDSM_X4_T(bfl[2*np][0], bfl[2*np][1], bfl[2*np+1][0], bfl[2*np+1][1],
                          smem_u32(Bl + (ks * 16 + brow) * BSTR + n0 + lch));
            }
            #pragma unroll
            for (int i = 0; i < 4; ++i)
                #pragma unroll
                for (int j = 0; j < 4; ++j) {
                    mma16816(acc[i][j], afl[i], bfh[j][0], bfh[j][1]);
                    mma16816(acc[i][j], afh[i], bfl[j][0], bfl[j][1]);
                    mma16816(acc[i][j], afh[i], bfh[j][0], bfh[j][1]);
                }
        }
    }

    // ---- epilogue ----
    #pragma unroll
    for (int i = 0; i < 4; ++i) {
        const int r1 = rowg0 + wm * 64 + i * 16 + g;
        #pragma unroll
        for (int j = 0; j < 4; ++j) {
            const int cgl = nblk + wn * 32 + j * 8 + tig * 2;
            if (MODE == 0) {
                const int which = cgl >> 10;
                const int head  = (cgl >> 6) & 15;
                const int dd    = cgl & 63;
                #pragma unroll
                for (int h2 = 0; h2 < 2; ++h2) {
                    const int r = r1 + h2 * 8;
                    const int b = r >> 11, n = r & 2047;
                    const size_t off = ((size_t)(b * HH + head) * NN + n) * DD + dd;
                    float a0 = acc[i][j][h2 * 2], a1 = acc[i][j][h2 * 2 + 1];
                    if (which == 0)      *(float2*)(g_q + off) = make_float2(a0, a1);
                    else if (which == 1) *(float2*)(g_k + off) = make_float2(a0, a1);
                    else {
                        uint32_t hi, lo;
                        splitp(a0, a1, hi, lo);
                        *(uint32_t*)(g_vh + off) = hi;
                        *(uint32_t*)(g_vl + off) = lo;
                    }
                }
            } else {
                const float2 bv = *(const float2*)(bias + cgl);
                #pragma unroll
                for (int h2 = 0; h2 < 2; ++h2) {
                    const int r = r1 + h2 * 8;
                    *(float2*)(Cout + (size_t)r * Nn + cgl) =
                        make_float2(acc[i][j][h2 * 2] + bv.x,
                                    acc[i][j][h2 * 2 + 1] + bv.y);
                }
            }
        }
    }
}

// ===========================================================================
// Per-head LayerNorm (D=64) on q,k; q scaled by sqrt(D)=8; fp16 hi/lo output.
// ===========================================================================
__global__ __launch_bounds__(128)
void qk_ln_kernel(const float* __restrict__ ln_w, const float* __restrict__ ln_b)
{
    const int R = BB * HH * NN;
    int row  = blockIdx.x * 4 + (threadIdx.x >> 5);
    int lane = threadIdx.x & 31;

    const bool isq = (row < R);
    const float* src = isq ? g_q : g_k;
    __half* dh = isq ? g_qh : g_kh;
    __half* dl = isq ? g_ql : g_kl;
    float extra = isq ? 8.0f : 1.0f;
    int r = isq ? row : (row - R);

    const float* p = src + (size_t)r * DD;
    float x0 = p[lane];
    float x1 = p[lane + 32];
    float s  = x0 + x1;
    float ss = x0 * x0 + x1 * x1;
    #pragma unroll
    for (int o = 16; o > 0; o >>= 1) {
        s  += __shfl_xor_sync(0xffffffffu, s,  o);
        ss += __shfl_xor_sync(0xffffffffu, ss, o);
    }
    float mu  = s * (1.0f / 64.0f);
    float var = ss * (1.0f / 64.0f) - mu * mu;
    float inv = rsqrtf(var + 1e-5f);
    float y0 = ((x0 - mu) * inv * ln_w[lane]      + ln_b[lane])      * extra;
    float y1 = ((x1 - mu) * inv * ln_w[lane + 32] + ln_b[lane + 32]) * extra;

    __half h0 = __float2half_rn(y0);
    __half h1 = __float2half_rn(y1);
    size_t off = (size_t)r * DD + lane;
    dh[off]      = h0;
    dh[off + 32] = h1;
    dl[off]      = __float2half_rn(y0 - __half2float(h0));
    dl[off + 32] = __float2half_rn(y1 - __half2float(h1));
}

// ===========================================================================
// Tensor-core causal flash attention, pre-split fp16, cp.async double-buffer,
// ONE sync per key tile.  CTA: 128 q-rows; 8 warps x 16 rows; key tile 64.
// ===========================================================================
#define FSTR 72                         // smem row stride (halves)
#define ARRB (64 * FSTR * 2)            // 9216 B per array
#define BUFB (4 * ARRB)                 // 36864 B per KV buffer
#define FL_SMEM (2 * BUFB)              // 73728 B

__global__ __launch_bounds__(256)
void flash_mma()
{
    extern __shared__ __align__(1024) char fsm[];
    const uint32_t fsmb = smem_u32(fsm);

    const int bh  = blockIdx.y;
    const int qi  = (gridDim.x - 1) - blockIdx.x;   // heavy tiles first
    const int tid = threadIdx.x;
    const int wid = tid >> 5, lane = tid & 31;
    const int g   = lane >> 2, tig = lane & 3;

    const size_t hb = (size_t)bh * NN * DD;
    const size_t qb = hb + (size_t)qi * 128 * DD;

    // ---- stage Q hi/lo into smem, extract per-warp a-frags ----
    {
        __half* Qh = (__half*)fsm;
        __half* Ql = (__half*)(fsm + 18432);
        #pragma unroll
        for (int s = 0; s < 4; ++s) {
            int idx = tid + s * 256;
            int row = idx >> 3, ch = idx & 7;
            *(uint4*)&Qh[row * FSTR + ch * 8] = *(const uint4*)(g_qh + qb + row * 64 + ch * 8);
            *(uint4*)&Ql[row * FSTR + ch * 8] = *(const uint4*)(g_ql + qb + row * 64 + ch * 8);
        }
    }
    __syncthreads();

    uint32_t qh[4][4], ql[4][4];
    {
        const int lr = lane & 15, lc = (lane >> 4) << 3;
        #pragma unroll
        for (int kk = 0; kk < 4; ++kk) {
            uint32_t a = fsmb + ((wid * 16 + lr) * FSTR + kk * 16 + lc) * 2;
            LDSM_X4(qh[kk][0], qh[kk][1], qh[kk][2], qh[kk][3], a);
            LDSM_X4(ql[kk][0], ql[kk][1], ql[kk][2], ql[kk][3], a + 18432);
        }
    }
    __syncthreads();

    auto issueKV = [&](int kj, int b) {
        const size_t kb = hb + (size_t)kj * 64 * DD;
        const uint32_t sb = fsmb + b * BUFB;
        const __half* gs[4] = { g_kh + kb, g_kl + kb, g_vh + kb, g_vl + kb };
        #pragma unroll
        for (int a = 0; a < 4; ++a) {
            const uint32_t so = sb + a * ARRB;
            #pragma unroll
            for (int s = 0; s < 2; ++s) {
                int idx = tid + s * 256;
                int row = idx >> 3, ch = idx & 7;
                CPA16(so + (row * FSTR + ch * 8) * 2, gs[a] + row * 64 + ch * 8);
            }
        }
    };

    float m0 = -1e30f, m1 = -1e30f, l0 = 0.0f, l1 = 0.0f;
    float o[8][4];
    #pragma unroll
    for (int j = 0; j < 8; ++j)
        #pragma unroll
        for (int r = 0; r < 4; ++r) o[j][r] = 0.0f;

    const int lrow = lane & 15, lch = (lane >> 4) << 3;
    const int brow = ((lane >> 3) & 1) * 8 + (lane & 7);
    const int kend = 2 * qi + 1;

    issueKV(0, 0);
    CPA_COMMIT();

    for (int kj = 0; kj <= kend; ++kj) {
        CPA_WAIT(0);
        __syncthreads();                 // tile kj ready; opposite buffer free
        if (kj < kend) {
            issueKV(kj + 1, (kj + 1) & 1);
            CPA_COMMIT();
        }

        const uint32_t bK  = fsmb + (kj & 1) * BUFB;           // K hi
        const uint32_t bKl = bK + ARRB;                        // K lo
        const uint32_t bV  = bK + 2 * ARRB;                    // V hi
        const uint32_t bVl = bK + 3 * ARRB;                    // V lo

        // ---- S = Q K^T (fp16 3-term, non-trans b-frags) ----
        float sf[8][4];
        #pragma unroll
        for (int j = 0; j < 8; ++j)
            #pragma unroll
            for (int r = 0; r < 4; ++r) sf[j][r] = 0.0f;

        #pragma unroll
        for (int kk = 0; kk < 4; ++kk) {
            #pragma unroll
            for (int jp = 0; jp < 4; ++jp) {
                const uint32_t off = ((jp * 16 + lrow) * FSTR + kk * 16 + lch) * 2;
                uint32_t h0, h1, h2, h3, e0, e1, e2, e3;
                LDSM_X4(h0, h1, h2, h3, bK + off);
                LDSM_X4(e0, e1, e2, e3, bKl + off);
                mma16816(sf[2*jp],   ql[kk], h0, h2);
                mma16816(sf[2*jp],   qh[kk], e0, e2);
                mma16816(sf[2*jp],   qh[kk], h0, h2);
                mma16816(sf[2*jp+1], ql[kk], h1, h3);
                mma16816(sf[2*jp+1], qh[kk], e1, e3);
                mma16816(sf[2*jp+1], qh[kk], h1, h3);
            }
        }

        // ---- causal mask on diagonal tiles ----
        if (kj >= 2 * qi) {
            const int row0 = qi * 128 + wid * 16 + g;
            const int row1 = row0 + 8;
            #pragma unroll
            for (int j = 0; j < 8; ++j) {
                const int c0 = kj * 64 + j * 8 + tig * 2;
                if (row0 < c0)     sf[j][0] = -1e30f;
                if (row0 < c0 + 1) sf[j][1] = -1e30f;
                if (row1 < c0)     sf[j][2] = -1e30f;
                if (row1 < c0 + 1) sf[j][3] = -1e30f;
            }
        }

        // ---- online softmax (rows g, g+8; quad-replicated over tig) ----
        float mx0 = -1e30f, mx1 = -1e30f;
        #pragma unroll
        for (int j = 0; j < 8; ++j) {
            mx0 = fmaxf(mx0, fmaxf(sf[j][0], sf[j][1]));
            mx1 = fmaxf(mx1, fmaxf(sf[j][2], sf[j][3]));
        }
        mx0 = fmaxf(mx0, __shfl_xor_sync(0xffffffffu, mx0, 1));
        mx0 = fmaxf(mx0, __shfl_xor_sync(0xffffffffu, mx0, 2));
        mx1 = fmaxf(mx1, __shfl_xor_sync(0xffffffffu, mx1, 1));
        mx1 = fmaxf(mx1, __shfl_xor_sync(0xffffffffu, mx1, 2));
        float mn0 = fmaxf(m0, mx0), mn1 = fmaxf(m1, mx1);
        float a0 = __expf(m0 - mn0), a1 = __expf(m1 - mn1);
        m0 = mn0; m1 = mn1;
        float rs0 = 0.0f, rs1 = 0.0f;
        #pragma unroll
        for (int j = 0; j < 8; ++j) {
            sf[j][0] = __expf(sf[j][0] - mn0); rs0 += sf[j][0];
            sf[j][1] = __expf(sf[j][1] - mn0); rs0 += sf[j][1];
            sf[j][2] = __expf(sf[j][2] - mn1); rs1 += sf[j][2];
            sf[j][3] = __expf(sf[j][3] - mn1); rs1 += sf[j][3];
        }
        rs0 += __shfl_xor_sync(0xffffffffu, rs0, 1);
        rs0 += __shfl_xor_sync(0xffffffffu, rs0, 2);
        rs1 += __shfl_xor_sync(0xffffffffu, rs1, 1);
        rs1 += __shfl_xor_sync(0xffffffffu, rs1, 2);
        l0 = l0 * a0 + rs0;
        l1 = l1 * a1 + rs1;
        #pragma unroll
        for (int j = 0; j < 8; ++j) {
            o[j][0] *= a0; o[j][1] *= a0;
            o[j][2] *= a1; o[j][3] *= a1;
        }

        // ---- P fragments (fp16 hi + lo) from S c-frags ----
        uint32_t ph[4][4], pl[4][4];
        #pragma unroll
        for (int t = 0; t < 4; ++t) {
            const int j0 = 2 * t, j1 = 2 * t + 1;
            splitp(sf[j0][0], sf[j0][1], ph[t][0], pl[t][0]);
            splitp(sf[j0][2], sf[j0][3], ph[t][1], pl[t][1]);
            splitp(sf[j1][0], sf[j1][1], ph[t][2], pl[t][2]);
            splitp(sf[j1][2], sf[j1][3], ph[t][3], pl[t][3]);
        }

        // ---- O += P V  (fp16 3-term, V frags via ldmatrix.x4.trans) ----
        #pragma unroll
        for (int t = 0; t < 4; ++t) {
            const int row = t * 16 + brow;
            #pragma unroll
            for (int jp = 0; jp < 4; ++jp) {
                const uint32_t off = (row * FSTR + jp * 16 + lch) * 2;
                uint32_t h0, h1, h2, h3, e0, e1, e2, e3;
                LDSM_X4_T(h0, h1, h2, h3, bV + off);
                LDSM_X4_T(e0, e1, e2, e3, bVl + off);
                mma16816(o[2 * jp],     pl[t], h0, h1);
                mma16816(o[2 * jp],     ph[t], e0, e1);
                mma16816(o[2 * jp],     ph[t], h0, h1);
                mma16816(o[2 * jp + 1], pl[t], h2, h3);
                mma16816(o[2 * jp + 1], ph[t], e2, e3);
                mma16816(o[2 * jp + 1], ph[t], h2, h3);
            }
        }
    }

    // ---- finalize, write ao as fp16 hi/lo [B,N,(H D)] ----
    const int b = bh >> 4;
    const int h = bh & 15;
    const float inv0 = 1.0f / l0, inv1 = 1.0f / l1;
    const int n0 = qi * 128 + wid * 16 + g;
    const int n1 = n0 + 8;
    #pragma unroll
    for (int j = 0; j < 8; ++j) {
        const int d = j * 8 + tig * 2;
        const size_t o0 = (((size_t)b * NN + n0) * HH + h) * DD + d;
        const size_t o1 = (((size_t)b * NN + n1) * HH + h) * DD + d;
        uint32_t hi, lo;
        splitp(o[j][0] * inv0, o[j][1] * inv0, hi, lo);
        *(uint32_t*)(g_aoh + o0) = hi;
        *(uint32_t*)(g_aol + o0) = lo;
        splitp(o[j][2] * inv1, o[j][3] * inv1, hi, lo);
        *(uint32_t*)(g_aoh + o1) = hi;
        *(uint32_t*)(g_aol + o1) = lo;
    }
}

// ===========================================================================
extern "C" void kernel_launch(void* const* d_in, const int* in_sizes, int n_in,
                              void* d_out, int out_size)
{
    const float* x      = (const float*)d_in[0];
    const float* w_qkv  = (const float*)d_in[1];
    const float* w_proj = (const float*)d_in[2];
    const float* b_proj = (const float*)d_in[3];
    const float* ln_w   = (const float*)d_in[4];
    const float* ln_b   = (const float*)d_in[5];
    float* out = (float*)d_out;

    cudaFuncSetAttribute(tc_gemm<0>, cudaFuncAttributeMaxDynamicSharedMemorySize, GEMM_SMEM);
    cudaFuncSetAttribute(tc_gemm<1>, cudaFuncAttributeMaxDynamicSharedMemorySize, GEMM_SMEM);
    cudaFuncSetAttribute(flash_mma, cudaFuncAttributeMaxDynamicSharedMemorySize, FL_SMEM);

    __half *xh, *xl, *wqh, *wql, *wph, *wpl;
    cudaGetSymbolAddress((void**)&xh,  g_xh);  cudaGetSymbolAddress((void**)&xl,  g_xl);
    cudaGetSymbolAddress((void**)&wqh, g_wqh); cudaGetSymbolAddress((void**)&wql, g_wql);
    cudaGetSymbolAddress((void**)&wph, g_wph); cudaGetSymbolAddress((void**)&wpl, g_wpl);

    // 0) pre-split operands to fp16 hi/lo
    f2h_split<<<4096, 256>>>(x,      xh,  xl,  BB*NN*CC/4);
    f2h_split<<<3072, 256>>>(w_qkv,  wqh, wql, CC*3*CC/4);
    f2h_split<<<1024, 256>>>(w_proj, wph, wpl, CC*CC/4);

    // 1) QKV projection -> q/k fp32, v fp16 hi/lo
    tc_gemm<0><<<dim3(24, 32), 256, GEMM_SMEM>>>(nullptr, nullptr);

    // 2) per-head LayerNorm on q,k -> fp16 hi/lo
    qk_ln_kernel<<<(2 * BB * HH * NN) / 4, 128>>>(ln_w, ln_b);

    // 3) causal flash attention -> ao fp16 hi/lo
    flash_mma<<<dim3(NN / 128, BB * HH), 256, FL_SMEM>>>();

    // 4) output projection + bias
    tc_gemm<1><<<dim3(8, 32), 256, GEMM_SMEM>>>(b_proj, out);
}